// round 10
// baseline (speedup 1.0000x reference)
#include <cuda_runtime.h>
#include <cuda_fp16.h>
#include <math.h>
#include <cstdint>

#define KTOT 2048
#define NJ   40
#define NT   5
#define NKC  128            // 2048/16 k-steps total
#define NBIAS 16
#define NSPL 16             // prep K-splits
#define SMARGIN 0.31f
#define RSCALE 2048.0f
#define RINV   (1.0f / 2048.0f)
#define XBYTES 34816u       // main: 128 rows * 272 B
#define BBYTES 10240u
#define BUFB   (XBYTES + BBYTES)
#define PXB    17408u       // prep: 64 rows * 272 B
#define PBUF   (PXB + BBYTES)

// ---- device scratch -------------------------------------------------------
__device__ float g_c[NJ];
__device__ float g_cpart[NBIAS * NJ];
__device__ float g_part[NSPL * KTOT * NJ];
__device__ uint2 g_Bfh[NKC * NT * 32];   // fp16 hi fragments
__device__ uint2 g_Bfl[NKC * NT * 32];   // fp16 residual*2048 fragments

// ---- helpers --------------------------------------------------------------
__device__ __forceinline__ uint32_t smem_u32(const void* p) {
    uint32_t a;
    asm("{ .reg .u64 t; cvta.to.shared.u64 t, %1; cvt.u32.u64 %0, t; }" : "=r"(a) : "l"(p));
    return a;
}
__device__ __forceinline__ void cp_async16(uint32_t d, const void* s) {
    asm volatile("cp.async.cg.shared.global [%0], [%1], 16;" :: "r"(d), "l"(s));
}
__device__ __forceinline__ void cp_commit() { asm volatile("cp.async.commit_group;" ::: "memory"); }
__device__ __forceinline__ void cp_wait0()  { asm volatile("cp.async.wait_group 0;" ::: "memory"); }

#define MMA_F16(d, a0, a1, a2, a3, b0, b1)                                    \
    asm volatile("mma.sync.aligned.m16n8k16.row.col.f32.f16.f16.f32 "         \
                 "{%0,%1,%2,%3}, {%4,%5,%6,%7}, {%8,%9}, {%0,%1,%2,%3};\n"    \
                 : "+f"(d[0]), "+f"(d[1]), "+f"(d[2]), "+f"(d[3])             \
                 : "r"(a0), "r"(a1), "r"(a2), "r"(a3), "r"(b0), "r"(b1))

__device__ __forceinline__ void cvt_split_h(float2 v, unsigned& h, unsigned& l) {
    __half2 hh = __floats2half2_rn(v.x, v.y);
    float2 hf = __half22float2(hh);
    __half2 ll = __floats2half2_rn((v.x - hf.x) * RSCALE, (v.y - hf.y) * RSCALE);
    h = *reinterpret_cast<unsigned*>(&hh);
    l = *reinterpret_cast<unsigned*>(&ll);
}
__device__ __forceinline__ unsigned pack_h2(float a, float b) {
    __half2 h = __floats2half2_rn(a, b);
    return *reinterpret_cast<unsigned*>(&h);
}

// ---------------------------------------------------------------------------
// Prep 1 (mma): g_part[split] = W_enc @ [Wcls|Wfl]
// grid 512 = 32 m-tiles (64 rows) x 16 K-splits, 128 threads (4 warps).
// smem 2x27648 -> 2+ CTAs/SM.  fp16 3-term split, fp32 partials out.
// ---------------------------------------------------------------------------
__device__ __forceinline__ void prep_stage(uint32_t smb, int buf, int koff,
                                           const float* __restrict__ Wenc, int tilebase,
                                           const float* __restrict__ Wcls,
                                           const float* __restrict__ Wfl, int tid) {
    uint32_t xd = smb + (uint32_t)buf * PBUF;
#pragma unroll
    for (int it = 0; it < 8; it++) {
        int q = it * 128 + tid;               // 1024 float4 for 64 rows
        int rw = q >> 4, c4 = q & 15;
        cp_async16(xd + (uint32_t)(rw * 272 + c4 * 16),
                   Wenc + (size_t)(tilebase + rw) * KTOT + koff + c4 * 4);
    }
    uint32_t wd = xd + PXB;
#pragma unroll
    for (int it = 0; it < 5; it++) {
        int q = it * 128 + tid;               // 640 float4
        int k = q / 10, j4 = q - k * 10;
        const float* src = (j4 < 5) ? (Wcls + (size_t)(koff + k) * 20 + j4 * 4)
                                    : (Wfl  + (size_t)(koff + k) * 20 + (j4 - 5) * 4);
        cp_async16(wd + (uint32_t)(k * 160 + j4 * 16), src);
    }
}

__global__ __launch_bounds__(128)
void prep_mma_kernel(const float* __restrict__ Wenc,
                     const float* __restrict__ Wcls, const float* __restrict__ Wfl) {
    extern __shared__ char sm[];
    const int tid = threadIdx.x;
    const int warp = tid >> 5, lane = tid & 31;
    const int c2 = (lane & 3) * 2;
    const int tile = blockIdx.x & 31, split = blockIdx.x >> 5;
    const int tilebase = tile * 64;
    const int kbeg = split * (KTOT / NSPL);   // 128-k span = 2 chunks

    const uint32_t smb = smem_u32(sm);
    prep_stage(smb, 0, kbeg, Wenc, tilebase, Wcls, Wfl, tid);
    cp_commit(); cp_wait0();
    __syncthreads();

    float acc1[NT][4], acc2[NT][4];
#pragma unroll
    for (int nt = 0; nt < NT; nt++)
#pragma unroll
        for (int e = 0; e < 4; e++) { acc1[nt][e] = 0.f; acc2[nt][e] = 0.f; }

    const uint32_t xoff = (uint32_t)((warp * 16 + (lane >> 2)) * 272 + c2 * 4);
    const uint32_t woff = (uint32_t)(((lane & 3) * 2 * 40 + (lane >> 2)) * 4);

    for (int c = 0; c < 2; c++) {
        int buf = c & 1;
        if (c == 0) {
            prep_stage(smb, 1, kbeg + 64, Wenc, tilebase, Wcls, Wfl, tid);
            cp_commit();
        }
        uint32_t base = smb + (uint32_t)buf * PBUF;
        uint32_t xa = base + xoff;
        uint32_t wsb = base + PXB + woff;
#pragma unroll
        for (int s = 0; s < 4; s++) {
            float2 v00, v10, v01, v11;
            asm("ld.shared.v2.f32 {%0, %1}, [%2];" : "=f"(v00.x), "=f"(v00.y) : "r"(xa + s * 64));
            asm("ld.shared.v2.f32 {%0, %1}, [%2];" : "=f"(v10.x), "=f"(v10.y) : "r"(xa + s * 64 + 8 * 272));
            asm("ld.shared.v2.f32 {%0, %1}, [%2];" : "=f"(v01.x), "=f"(v01.y) : "r"(xa + s * 64 + 32));
            asm("ld.shared.v2.f32 {%0, %1}, [%2];" : "=f"(v11.x), "=f"(v11.y) : "r"(xa + s * 64 + 32 + 8 * 272));
            unsigned ah0, ah1, ah2, ah3, al0, al1, al2, al3;
            cvt_split_h(v00, ah0, al0);
            cvt_split_h(v10, ah1, al1);
            cvt_split_h(v01, ah2, al2);
            cvt_split_h(v11, ah3, al3);
            uint32_t ka = wsb + (uint32_t)(s * 16 * 160);
#pragma unroll
            for (int nt = 0; nt < NT; nt++) {
                float w00, w01, w10, w11;
                uint32_t a = ka + (uint32_t)(nt * 32);
                asm("ld.shared.f32 %0, [%1];" : "=f"(w00) : "r"(a));
                asm("ld.shared.f32 %0, [%1];" : "=f"(w01) : "r"(a + 160));
                asm("ld.shared.f32 %0, [%1];" : "=f"(w10) : "r"(a + 8 * 160));
                asm("ld.shared.f32 %0, [%1];" : "=f"(w11) : "r"(a + 9 * 160));
                unsigned bh0, bl0, bh1, bl1;
                cvt_split_h(make_float2(w00, w01), bh0, bl0);
                cvt_split_h(make_float2(w10, w11), bh1, bl1);
                MMA_F16(acc1[nt], ah0, ah1, ah2, ah3, bh0, bh1);
                MMA_F16(acc2[nt], al0, al1, al2, al3, bh0, bh1);
                MMA_F16(acc2[nt], ah0, ah1, ah2, ah3, bl0, bl1);
            }
        }
        if (c == 0) cp_wait0();
        __syncthreads();
    }

    int krow = tilebase + warp * 16 + (lane >> 2);
#pragma unroll
    for (int nt = 0; nt < NT; nt++) {
        float* p0 = g_part + ((size_t)split * KTOT + krow) * NJ + nt * 8 + c2;
        float* p1 = p0 + 8 * NJ;
        *(float2*)p0 = make_float2(acc1[nt][0] + acc2[nt][0] * RINV,
                                   acc1[nt][1] + acc2[nt][1] * RINV);
        *(float2*)p1 = make_float2(acc1[nt][2] + acc2[nt][2] * RINV,
                                   acc1[nt][3] + acc2[nt][3] * RINV);
    }
}

// ---------------------------------------------------------------------------
// Prep 2: blocks 0..31: coalesced reduce of a 64-row W12 slab + fragment pack;
//         blocks 32..47: bias partials; block 32 inits g_c raw biases.
// ---------------------------------------------------------------------------
__global__ __launch_bounds__(256)
void bsplit_bias_kernel(const float* __restrict__ benc,
                        const float* __restrict__ Wcls, const float* __restrict__ Wfl,
                        const float* __restrict__ bcls, const float* __restrict__ bfl) {
    int b = blockIdx.x;
    int tid = threadIdx.x;
    if (b < 32) {
        __shared__ float w12[64 * NJ];           // 2560 floats
        // phase 1: coalesced reduce 16 split slabs
        float r[10];
#pragma unroll
        for (int i = 0; i < 10; i++) r[i] = 0.f;
        size_t cellbase = (size_t)b * 2560;
#pragma unroll
        for (int s = 0; s < NSPL; s++) {
            const float* src = g_part + (size_t)s * (KTOT * NJ) + cellbase;
#pragma unroll
            for (int i = 0; i < 10; i++) r[i] += src[tid + i * 256];
        }
#pragma unroll
        for (int i = 0; i < 10; i++) w12[tid + i * 256] = r[i];
        __syncthreads();
        // phase 2: pack 640 fragment slots (contiguous global indices)
#pragma unroll
        for (int i = 0; i < 3; i++) {
            int f = tid + i * 256;
            if (f < 640) {
                int kc16l = f / 160;
                int rem = f - kc16l * 160;
                int nt = rem >> 5, lane = rem & 31;
                int k0l = kc16l * 16 + (lane & 3) * 2;
                int n = nt * 8 + (lane >> 2);
                float v[4], rr[4];
#pragma unroll
                for (int e = 0; e < 4; e++) {
                    v[e] = w12[(k0l + (e >> 1) * 8 + (e & 1)) * NJ + n];
                    __half h = __float2half_rn(v[e]);
                    rr[e] = (v[e] - __half2float(h)) * RSCALE;
                }
                int gi = b * 640 + f;
                g_Bfh[gi] = make_uint2(pack_h2(v[0], v[1]), pack_h2(v[2], v[3]));
                g_Bfl[gi] = make_uint2(pack_h2(rr[0], rr[1]), pack_h2(rr[2], rr[3]));
            }
        }
        return;
    }
    // bias blocks
    __shared__ float sw[4][NJ];
    int bb = b - 32;
    if (tid >= 128) return;
    int k = bb * 128 + tid;
    int warp = tid >> 5, lane = tid & 31;
    float bv = benc[k];
    float w[NJ];
#pragma unroll
    for (int j4 = 0; j4 < 5; j4++) {
        float4 v = *(const float4*)(Wcls + (size_t)k * 20 + j4 * 4);
        w[j4*4+0] = v.x; w[j4*4+1] = v.y; w[j4*4+2] = v.z; w[j4*4+3] = v.w;
    }
#pragma unroll
    for (int j4 = 0; j4 < 5; j4++) {
        float4 v = *(const float4*)(Wfl + (size_t)k * 20 + j4 * 4);
        w[20+j4*4+0] = v.x; w[20+j4*4+1] = v.y; w[20+j4*4+2] = v.z; w[20+j4*4+3] = v.w;
    }
#pragma unroll
    for (int j = 0; j < NJ; j++) {
        float s = bv * w[j];
#pragma unroll
        for (int o = 16; o > 0; o >>= 1) s += __shfl_xor_sync(0xffffffffu, s, o);
        if (lane == 0) sw[warp][j] = s;
    }
    __syncthreads();
    if (tid < NJ) {
        g_cpart[bb * NJ + tid] = (sw[0][tid] + sw[1][tid]) + (sw[2][tid] + sw[3][tid]);
        if (bb == 0) g_c[tid] = (tid < 20) ? bcls[tid] : bfl[tid - 20];
    }
}

// ---------------------------------------------------------------------------
// Main kernel (UNCHANGED from R9): 128 rows x 40 cols per CTA, fp16 3-term
// mma.sync, double-buffered cp.async, fused dual-softmax epilogue.
// ---------------------------------------------------------------------------
__device__ __forceinline__ void stage_chunk(uint32_t smb, int buf, int c,
                                            const float* __restrict__ x,
                                            size_t growbase, int tid) {
    uint32_t xd = smb + (uint32_t)buf * BUFB;
#pragma unroll
    for (int it = 0; it < 8; it++) {
        int q = it * 256 + tid;
        int rw = q >> 4, c4 = q & 15;
        cp_async16(xd + (uint32_t)(rw * 272 + c4 * 16),
                   x + (growbase + rw) * KTOT + c * 64 + c4 * 4);
    }
    uint32_t bd = xd + XBYTES;
    const char* srcH = (const char*)(g_Bfh + (size_t)c * 640);
    const char* srcL = (const char*)(g_Bfl + (size_t)c * 640);
#pragma unroll
    for (int it = 0; it < 3; it++) {
        int q = it * 256 + tid;
        if (q < 320)      cp_async16(bd + (uint32_t)q * 16, srcH + q * 16);
        else if (q < 640) cp_async16(bd + 5120u + (uint32_t)(q - 320) * 16, srcL + (q - 320) * 16);
    }
}

__global__ __launch_bounds__(256, 1)
void mma_main_kernel(const float* __restrict__ x, float* __restrict__ out) {
    extern __shared__ char sm[];
    __shared__ float cb[NJ];
    const int tid = threadIdx.x;
    const int warp = tid >> 5, lane = tid & 31;
    const int c2 = (lane & 3) * 2;
    const size_t growbase = (size_t)blockIdx.x * 128;

    if (tid < NJ) {
        float s = g_c[tid];
#pragma unroll
        for (int p = 0; p < NBIAS; p++) s += g_cpart[p * NJ + tid];
        cb[tid] = s;
    }

    const uint32_t smb = smem_u32(sm);
    stage_chunk(smb, 0, 0, x, growbase, tid);
    cp_commit(); cp_wait0();
    __syncthreads();

    float acc1[NT][4], acc2[NT][4];
#pragma unroll
    for (int nt = 0; nt < NT; nt++)
#pragma unroll
        for (int e = 0; e < 4; e++) { acc1[nt][e] = 0.f; acc2[nt][e] = 0.f; }

    const uint32_t xoff = (uint32_t)((warp * 16 + (lane >> 2)) * 272 + c2 * 4);

    for (int c = 0; c < 32; c++) {
        int buf = c & 1;
        if (c + 1 < 32) { stage_chunk(smb, buf ^ 1, c + 1, x, growbase, tid); cp_commit(); }
        uint32_t base = smb + (uint32_t)buf * BUFB;
        uint32_t xa = base + xoff;
        uint32_t ba = base + XBYTES + (uint32_t)lane * 8;
#pragma unroll
        for (int s = 0; s < 4; s++) {
            float2 v00, v10, v01, v11;
            asm("ld.shared.v2.f32 {%0, %1}, [%2];" : "=f"(v00.x), "=f"(v00.y) : "r"(xa + s * 64));
            asm("ld.shared.v2.f32 {%0, %1}, [%2];" : "=f"(v10.x), "=f"(v10.y) : "r"(xa + s * 64 + 8 * 272));
            asm("ld.shared.v2.f32 {%0, %1}, [%2];" : "=f"(v01.x), "=f"(v01.y) : "r"(xa + s * 64 + 32));
            asm("ld.shared.v2.f32 {%0, %1}, [%2];" : "=f"(v11.x), "=f"(v11.y) : "r"(xa + s * 64 + 32 + 8 * 272));
            unsigned ah0, ah1, ah2, ah3, al0, al1, al2, al3;
            cvt_split_h(v00, ah0, al0);
            cvt_split_h(v10, ah1, al1);
            cvt_split_h(v01, ah2, al2);
            cvt_split_h(v11, ah3, al3);
#pragma unroll
            for (int nt = 0; nt < NT; nt++) {
                uint2 wh, wl;
                uint32_t fo = (uint32_t)((s * NT + nt) * 32) * 8;
                asm("ld.shared.v2.u32 {%0, %1}, [%2];" : "=r"(wh.x), "=r"(wh.y) : "r"(ba + fo));
                asm("ld.shared.v2.u32 {%0, %1}, [%2];" : "=r"(wl.x), "=r"(wl.y) : "r"(ba + fo + 5120));
                MMA_F16(acc1[nt], ah0, ah1, ah2, ah3, wh.x, wh.y);
                MMA_F16(acc2[nt], al0, al1, al2, al3, wh.x, wh.y);
                MMA_F16(acc2[nt], ah0, ah1, ah2, ah3, wl.x, wl.y);
            }
        }
        if (c + 1 < 32) cp_wait0();
        __syncthreads();
    }

    // ---- epilogue: combine scales, dual softmax + threshold ---------------
    int row0 = (int)growbase + warp * 16 + (lane >> 2);
    float scl[2];
    float ecls[2][6];
#pragma unroll
    for (int half = 0; half < 2; half++) {
        float m1 = -1e30f, m2 = -1e30f, mn2 = 1e30f;
#pragma unroll
        for (int nt = 0; nt < NT; nt++)
#pragma unroll
            for (int e = 0; e < 2; e++) {
                int j = nt * 8 + c2 + e;
                float v = acc1[nt][half * 2 + e] + acc2[nt][half * 2 + e] * RINV + cb[j];
                if (j < 20) m1 = fmaxf(m1, v);
                else { m2 = fmaxf(m2, v); mn2 = fminf(mn2, v); }
            }
        m1 = fmaxf(m1, __shfl_xor_sync(0xffffffffu, m1, 1));
        m1 = fmaxf(m1, __shfl_xor_sync(0xffffffffu, m1, 2));
        m2 = fmaxf(m2, __shfl_xor_sync(0xffffffffu, m2, 1));
        m2 = fmaxf(m2, __shfl_xor_sync(0xffffffffu, m2, 2));
        mn2 = fminf(mn2, __shfl_xor_sync(0xffffffffu, mn2, 1));
        mn2 = fminf(mn2, __shfl_xor_sync(0xffffffffu, mn2, 2));
        float s1 = 0.f, s2 = 0.f;
#pragma unroll
        for (int nt = 0; nt < NT; nt++)
#pragma unroll
            for (int e = 0; e < 2; e++) {
                int j = nt * 8 + c2 + e;
                float v = acc1[nt][half * 2 + e] + acc2[nt][half * 2 + e] * RINV + cb[j];
                if (j < 20) {
                    float ex = __expf(v - m1);
                    if (nt < 3) ecls[half][nt * 2 + e] = ex;
                    s1 += ex;
                } else {
                    s2 += __expf(v - m2);
                }
            }
        s1 += __shfl_xor_sync(0xffffffffu, s1, 1);
        s1 += __shfl_xor_sync(0xffffffffu, s1, 2);
        s2 += __shfl_xor_sync(0xffffffffu, s2, 1);
        s2 += __shfl_xor_sync(0xffffffffu, s2, 2);
        float pred = 1.0f / s1;
        float tau  = __expf(mn2 - m2) / s2;
        scl[half] = (pred >= tau + SMARGIN) ? pred : 0.0f;
    }
#pragma unroll
    for (int half = 0; half < 2; half++) {
        float* orow = out + (size_t)(row0 + half * 8) * 20;
#pragma unroll
        for (int nt = 0; nt < 3; nt++) {
            int j0 = nt * 8 + c2;
            if (j0 < 20)
                *(float2*)(orow + j0) = make_float2(ecls[half][nt * 2 + 0] * scl[half],
                                                    ecls[half][nt * 2 + 1] * scl[half]);
        }
    }
}

// ---------------------------------------------------------------------------
extern "C" void kernel_launch(void* const* d_in, const int* in_sizes, int n_in,
                              void* d_out, int out_size) {
    const float* x    = (const float*)d_in[0];
    const float* Wenc = (const float*)d_in[1];
    const float* benc = (const float*)d_in[2];
    const float* Wcls = (const float*)d_in[3];
    const float* bcls = (const float*)d_in[4];
    const float* Wfl  = (const float*)d_in[5];
    const float* bfl  = (const float*)d_in[6];
    float* out = (float*)d_out;
    int M = in_sizes[0] / KTOT;   // 16384

    static int smset = 0;
    if (!smset) {
        cudaFuncSetAttribute(mma_main_kernel,
                             cudaFuncAttributeMaxDynamicSharedMemorySize, 2 * BUFB);
        cudaFuncSetAttribute(prep_mma_kernel,
                             cudaFuncAttributeMaxDynamicSharedMemorySize, 2 * PBUF);
        smset = 1;
    }

    prep_mma_kernel<<<32 * NSPL, 128, 2 * PBUF>>>(Wenc, Wcls, Wfl);
    bsplit_bias_kernel<<<48, 256>>>(benc, Wcls, Wfl, bcls, bfl);
    mma_main_kernel<<<M / 128, 256, 2 * BUFB>>>(x, out);
}

// round 11
// speedup vs baseline: 1.0123x; 1.0123x over previous
#include <cuda_runtime.h>
#include <cuda_fp16.h>
#include <math.h>
#include <cstdint>

#define KTOT 2048
#define NJ   40
#define NT   5
#define NKC  128            // 2048/16 k-steps total
#define NBIAS 16
#define NSPL 16             // prep K-splits
#define SMARGIN 0.31f
#define RSCALE 2048.0f
#define RINV   (1.0f / 2048.0f)
#define XBYTES 34816u       // main: 128 rows * 272 B
#define BBYTES 10240u
#define BUFB   (XBYTES + BBYTES)
#define PXB    17408u       // prep: 64 rows * 272 B
#define PBUF   (PXB + BBYTES)

// ---- device scratch -------------------------------------------------------
__device__ float g_c[NJ];
__device__ float g_cpart[NBIAS * NJ];
__device__ float g_part[NSPL * KTOT * NJ];
__device__ uint2 g_Bfh[NKC * NT * 32];   // fp16 hi fragments
__device__ uint2 g_Bfl[NKC * NT * 32];   // fp16 residual*2048 fragments

// ---- helpers --------------------------------------------------------------
__device__ __forceinline__ uint32_t smem_u32(const void* p) {
    uint32_t a;
    asm("{ .reg .u64 t; cvta.to.shared.u64 t, %1; cvt.u32.u64 %0, t; }" : "=r"(a) : "l"(p));
    return a;
}
__device__ __forceinline__ void cp_async16(uint32_t d, const void* s) {
    asm volatile("cp.async.cg.shared.global [%0], [%1], 16;" :: "r"(d), "l"(s));
}
__device__ __forceinline__ void cp_commit() { asm volatile("cp.async.commit_group;" ::: "memory"); }
__device__ __forceinline__ void cp_wait0()  { asm volatile("cp.async.wait_group 0;" ::: "memory"); }

#define MMA_F16(d, a0, a1, a2, a3, b0, b1)                                    \
    asm volatile("mma.sync.aligned.m16n8k16.row.col.f32.f16.f16.f32 "         \
                 "{%0,%1,%2,%3}, {%4,%5,%6,%7}, {%8,%9}, {%0,%1,%2,%3};\n"    \
                 : "+f"(d[0]), "+f"(d[1]), "+f"(d[2]), "+f"(d[3])             \
                 : "r"(a0), "r"(a1), "r"(a2), "r"(a3), "r"(b0), "r"(b1))

__device__ __forceinline__ void cvt_split_h(float2 v, unsigned& h, unsigned& l) {
    __half2 hh = __floats2half2_rn(v.x, v.y);
    float2 hf = __half22float2(hh);
    __half2 ll = __floats2half2_rn((v.x - hf.x) * RSCALE, (v.y - hf.y) * RSCALE);
    h = *reinterpret_cast<unsigned*>(&hh);
    l = *reinterpret_cast<unsigned*>(&ll);
}
__device__ __forceinline__ unsigned pack_h2(float a, float b) {
    __half2 h = __floats2half2_rn(a, b);
    return *reinterpret_cast<unsigned*>(&h);
}

// ---------------------------------------------------------------------------
// Prep 1 (mma): g_part[split] = W_enc @ [Wcls|Wfl]
// grid 512 = 32 m-tiles (64 rows) x 16 K-splits, 128 threads (4 warps).
// smem 2x27648 -> 2+ CTAs/SM.  fp16 3-term split, fp32 partials out.
// ---------------------------------------------------------------------------
__device__ __forceinline__ void prep_stage(uint32_t smb, int buf, int koff,
                                           const float* __restrict__ Wenc, int tilebase,
                                           const float* __restrict__ Wcls,
                                           const float* __restrict__ Wfl, int tid) {
    uint32_t xd = smb + (uint32_t)buf * PBUF;
#pragma unroll
    for (int it = 0; it < 8; it++) {
        int q = it * 128 + tid;               // 1024 float4 for 64 rows
        int rw = q >> 4, c4 = q & 15;
        cp_async16(xd + (uint32_t)(rw * 272 + c4 * 16),
                   Wenc + (size_t)(tilebase + rw) * KTOT + koff + c4 * 4);
    }
    uint32_t wd = xd + PXB;
#pragma unroll
    for (int it = 0; it < 5; it++) {
        int q = it * 128 + tid;               // 640 float4
        int k = q / 10, j4 = q - k * 10;
        const float* src = (j4 < 5) ? (Wcls + (size_t)(koff + k) * 20 + j4 * 4)
                                    : (Wfl  + (size_t)(koff + k) * 20 + (j4 - 5) * 4);
        cp_async16(wd + (uint32_t)(k * 160 + j4 * 16), src);
    }
}

__global__ __launch_bounds__(128)
void prep_mma_kernel(const float* __restrict__ Wenc,
                     const float* __restrict__ Wcls, const float* __restrict__ Wfl) {
    extern __shared__ char sm[];
    const int tid = threadIdx.x;
    const int warp = tid >> 5, lane = tid & 31;
    const int c2 = (lane & 3) * 2;
    const int tile = blockIdx.x & 31, split = blockIdx.x >> 5;
    const int tilebase = tile * 64;
    const int kbeg = split * (KTOT / NSPL);   // 128-k span = 2 chunks

    const uint32_t smb = smem_u32(sm);
    prep_stage(smb, 0, kbeg, Wenc, tilebase, Wcls, Wfl, tid);
    cp_commit(); cp_wait0();
    __syncthreads();

    float acc1[NT][4], acc2[NT][4];
#pragma unroll
    for (int nt = 0; nt < NT; nt++)
#pragma unroll
        for (int e = 0; e < 4; e++) { acc1[nt][e] = 0.f; acc2[nt][e] = 0.f; }

    const uint32_t xoff = (uint32_t)((warp * 16 + (lane >> 2)) * 272 + c2 * 4);
    const uint32_t woff = (uint32_t)(((lane & 3) * 2 * 40 + (lane >> 2)) * 4);

    for (int c = 0; c < 2; c++) {
        int buf = c & 1;
        if (c == 0) {
            prep_stage(smb, 1, kbeg + 64, Wenc, tilebase, Wcls, Wfl, tid);
            cp_commit();
        }
        uint32_t base = smb + (uint32_t)buf * PBUF;
        uint32_t xa = base + xoff;
        uint32_t wsb = base + PXB + woff;
#pragma unroll
        for (int s = 0; s < 4; s++) {
            float2 v00, v10, v01, v11;
            asm("ld.shared.v2.f32 {%0, %1}, [%2];" : "=f"(v00.x), "=f"(v00.y) : "r"(xa + s * 64));
            asm("ld.shared.v2.f32 {%0, %1}, [%2];" : "=f"(v10.x), "=f"(v10.y) : "r"(xa + s * 64 + 8 * 272));
            asm("ld.shared.v2.f32 {%0, %1}, [%2];" : "=f"(v01.x), "=f"(v01.y) : "r"(xa + s * 64 + 32));
            asm("ld.shared.v2.f32 {%0, %1}, [%2];" : "=f"(v11.x), "=f"(v11.y) : "r"(xa + s * 64 + 32 + 8 * 272));
            unsigned ah0, ah1, ah2, ah3, al0, al1, al2, al3;
            cvt_split_h(v00, ah0, al0);
            cvt_split_h(v10, ah1, al1);
            cvt_split_h(v01, ah2, al2);
            cvt_split_h(v11, ah3, al3);
            uint32_t ka = wsb + (uint32_t)(s * 16 * 160);
#pragma unroll
            for (int nt = 0; nt < NT; nt++) {
                float w00, w01, w10, w11;
                uint32_t a = ka + (uint32_t)(nt * 32);
                asm("ld.shared.f32 %0, [%1];" : "=f"(w00) : "r"(a));
                asm("ld.shared.f32 %0, [%1];" : "=f"(w01) : "r"(a + 160));
                asm("ld.shared.f32 %0, [%1];" : "=f"(w10) : "r"(a + 8 * 160));
                asm("ld.shared.f32 %0, [%1];" : "=f"(w11) : "r"(a + 9 * 160));
                unsigned bh0, bl0, bh1, bl1;
                cvt_split_h(make_float2(w00, w01), bh0, bl0);
                cvt_split_h(make_float2(w10, w11), bh1, bl1);
                MMA_F16(acc1[nt], ah0, ah1, ah2, ah3, bh0, bh1);
                MMA_F16(acc2[nt], al0, al1, al2, al3, bh0, bh1);
                MMA_F16(acc2[nt], ah0, ah1, ah2, ah3, bl0, bl1);
            }
        }
        if (c == 0) cp_wait0();
        __syncthreads();
    }

    int krow = tilebase + warp * 16 + (lane >> 2);
#pragma unroll
    for (int nt = 0; nt < NT; nt++) {
        float* p0 = g_part + ((size_t)split * KTOT + krow) * NJ + nt * 8 + c2;
        float* p1 = p0 + 8 * NJ;
        *(float2*)p0 = make_float2(acc1[nt][0] + acc2[nt][0] * RINV,
                                   acc1[nt][1] + acc2[nt][1] * RINV);
        *(float2*)p1 = make_float2(acc1[nt][2] + acc2[nt][2] * RINV,
                                   acc1[nt][3] + acc2[nt][3] * RINV);
    }
}

// ---------------------------------------------------------------------------
// Prep 2: blocks 0..31: coalesced reduce of a 64-row W12 slab + fragment pack;
//         blocks 32..47: bias partials; block 32 inits g_c raw biases.
// ---------------------------------------------------------------------------
__global__ __launch_bounds__(256)
void bsplit_bias_kernel(const float* __restrict__ benc,
                        const float* __restrict__ Wcls, const float* __restrict__ Wfl,
                        const float* __restrict__ bcls, const float* __restrict__ bfl) {
    int b = blockIdx.x;
    int tid = threadIdx.x;
    if (b < 32) {
        __shared__ float w12[64 * NJ];           // 2560 floats
        // phase 1: coalesced reduce 16 split slabs
        float r[10];
#pragma unroll
        for (int i = 0; i < 10; i++) r[i] = 0.f;
        size_t cellbase = (size_t)b * 2560;
#pragma unroll
        for (int s = 0; s < NSPL; s++) {
            const float* src = g_part + (size_t)s * (KTOT * NJ) + cellbase;
#pragma unroll
            for (int i = 0; i < 10; i++) r[i] += src[tid + i * 256];
        }
#pragma unroll
        for (int i = 0; i < 10; i++) w12[tid + i * 256] = r[i];
        __syncthreads();
        // phase 2: pack 640 fragment slots (contiguous global indices)
#pragma unroll
        for (int i = 0; i < 3; i++) {
            int f = tid + i * 256;
            if (f < 640) {
                int kc16l = f / 160;
                int rem = f - kc16l * 160;
                int nt = rem >> 5, lane = rem & 31;
                int k0l = kc16l * 16 + (lane & 3) * 2;
                int n = nt * 8 + (lane >> 2);
                float v[4], rr[4];
#pragma unroll
                for (int e = 0; e < 4; e++) {
                    v[e] = w12[(k0l + (e >> 1) * 8 + (e & 1)) * NJ + n];
                    __half h = __float2half_rn(v[e]);
                    rr[e] = (v[e] - __half2float(h)) * RSCALE;
                }
                int gi = b * 640 + f;
                g_Bfh[gi] = make_uint2(pack_h2(v[0], v[1]), pack_h2(v[2], v[3]));
                g_Bfl[gi] = make_uint2(pack_h2(rr[0], rr[1]), pack_h2(rr[2], rr[3]));
            }
        }
        return;
    }
    // bias blocks
    __shared__ float sw[4][NJ];
    int bb = b - 32;
    if (tid >= 128) return;
    int k = bb * 128 + tid;
    int warp = tid >> 5, lane = tid & 31;
    float bv = benc[k];
    float w[NJ];
#pragma unroll
    for (int j4 = 0; j4 < 5; j4++) {
        float4 v = *(const float4*)(Wcls + (size_t)k * 20 + j4 * 4);
        w[j4*4+0] = v.x; w[j4*4+1] = v.y; w[j4*4+2] = v.z; w[j4*4+3] = v.w;
    }
#pragma unroll
    for (int j4 = 0; j4 < 5; j4++) {
        float4 v = *(const float4*)(Wfl + (size_t)k * 20 + j4 * 4);
        w[20+j4*4+0] = v.x; w[20+j4*4+1] = v.y; w[20+j4*4+2] = v.z; w[20+j4*4+3] = v.w;
    }
#pragma unroll
    for (int j = 0; j < NJ; j++) {
        float s = bv * w[j];
#pragma unroll
        for (int o = 16; o > 0; o >>= 1) s += __shfl_xor_sync(0xffffffffu, s, o);
        if (lane == 0) sw[warp][j] = s;
    }
    __syncthreads();
    if (tid < NJ) {
        g_cpart[bb * NJ + tid] = (sw[0][tid] + sw[1][tid]) + (sw[2][tid] + sw[3][tid]);
        if (bb == 0) g_c[tid] = (tid < 20) ? bcls[tid] : bfl[tid - 20];
    }
}

// ---------------------------------------------------------------------------
// Main kernel (UNCHANGED from R9): 128 rows x 40 cols per CTA, fp16 3-term
// mma.sync, double-buffered cp.async, fused dual-softmax epilogue.
// ---------------------------------------------------------------------------
__device__ __forceinline__ void stage_chunk(uint32_t smb, int buf, int c,
                                            const float* __restrict__ x,
                                            size_t growbase, int tid) {
    uint32_t xd = smb + (uint32_t)buf * BUFB;
#pragma unroll
    for (int it = 0; it < 8; it++) {
        int q = it * 256 + tid;
        int rw = q >> 4, c4 = q & 15;
        cp_async16(xd + (uint32_t)(rw * 272 + c4 * 16),
                   x + (growbase + rw) * KTOT + c * 64 + c4 * 4);
    }
    uint32_t bd = xd + XBYTES;
    const char* srcH = (const char*)(g_Bfh + (size_t)c * 640);
    const char* srcL = (const char*)(g_Bfl + (size_t)c * 640);
#pragma unroll
    for (int it = 0; it < 3; it++) {
        int q = it * 256 + tid;
        if (q < 320)      cp_async16(bd + (uint32_t)q * 16, srcH + q * 16);
        else if (q < 640) cp_async16(bd + 5120u + (uint32_t)(q - 320) * 16, srcL + (q - 320) * 16);
    }
}

__global__ __launch_bounds__(256, 1)
void mma_main_kernel(const float* __restrict__ x, float* __restrict__ out) {
    extern __shared__ char sm[];
    __shared__ float cb[NJ];
    const int tid = threadIdx.x;
    const int warp = tid >> 5, lane = tid & 31;
    const int c2 = (lane & 3) * 2;
    const size_t growbase = (size_t)blockIdx.x * 128;

    if (tid < NJ) {
        float s = g_c[tid];
#pragma unroll
        for (int p = 0; p < NBIAS; p++) s += g_cpart[p * NJ + tid];
        cb[tid] = s;
    }

    const uint32_t smb = smem_u32(sm);
    stage_chunk(smb, 0, 0, x, growbase, tid);
    cp_commit(); cp_wait0();
    __syncthreads();

    float acc1[NT][4], acc2[NT][4];
#pragma unroll
    for (int nt = 0; nt < NT; nt++)
#pragma unroll
        for (int e = 0; e < 4; e++) { acc1[nt][e] = 0.f; acc2[nt][e] = 0.f; }

    const uint32_t xoff = (uint32_t)((warp * 16 + (lane >> 2)) * 272 + c2 * 4);

    for (int c = 0; c < 32; c++) {
        int buf = c & 1;
        if (c + 1 < 32) { stage_chunk(smb, buf ^ 1, c + 1, x, growbase, tid); cp_commit(); }
        uint32_t base = smb + (uint32_t)buf * BUFB;
        uint32_t xa = base + xoff;
        uint32_t ba = base + XBYTES + (uint32_t)lane * 8;
#pragma unroll
        for (int s = 0; s < 4; s++) {
            float2 v00, v10, v01, v11;
            asm("ld.shared.v2.f32 {%0, %1}, [%2];" : "=f"(v00.x), "=f"(v00.y) : "r"(xa + s * 64));
            asm("ld.shared.v2.f32 {%0, %1}, [%2];" : "=f"(v10.x), "=f"(v10.y) : "r"(xa + s * 64 + 8 * 272));
            asm("ld.shared.v2.f32 {%0, %1}, [%2];" : "=f"(v01.x), "=f"(v01.y) : "r"(xa + s * 64 + 32));
            asm("ld.shared.v2.f32 {%0, %1}, [%2];" : "=f"(v11.x), "=f"(v11.y) : "r"(xa + s * 64 + 32 + 8 * 272));
            unsigned ah0, ah1, ah2, ah3, al0, al1, al2, al3;
            cvt_split_h(v00, ah0, al0);
            cvt_split_h(v10, ah1, al1);
            cvt_split_h(v01, ah2, al2);
            cvt_split_h(v11, ah3, al3);
#pragma unroll
            for (int nt = 0; nt < NT; nt++) {
                uint2 wh, wl;
                uint32_t fo = (uint32_t)((s * NT + nt) * 32) * 8;
                asm("ld.shared.v2.u32 {%0, %1}, [%2];" : "=r"(wh.x), "=r"(wh.y) : "r"(ba + fo));
                asm("ld.shared.v2.u32 {%0, %1}, [%2];" : "=r"(wl.x), "=r"(wl.y) : "r"(ba + fo + 5120));
                MMA_F16(acc1[nt], ah0, ah1, ah2, ah3, wh.x, wh.y);
                MMA_F16(acc2[nt], al0, al1, al2, al3, wh.x, wh.y);
                MMA_F16(acc2[nt], ah0, ah1, ah2, ah3, wl.x, wl.y);
            }
        }
        if (c + 1 < 32) cp_wait0();
        __syncthreads();
    }

    // ---- epilogue: combine scales, dual softmax + threshold ---------------
    int row0 = (int)growbase + warp * 16 + (lane >> 2);
    float scl[2];
    float ecls[2][6];
#pragma unroll
    for (int half = 0; half < 2; half++) {
        float m1 = -1e30f, m2 = -1e30f, mn2 = 1e30f;
#pragma unroll
        for (int nt = 0; nt < NT; nt++)
#pragma unroll
            for (int e = 0; e < 2; e++) {
                int j = nt * 8 + c2 + e;
                float v = acc1[nt][half * 2 + e] + acc2[nt][half * 2 + e] * RINV + cb[j];
                if (j < 20) m1 = fmaxf(m1, v);
                else { m2 = fmaxf(m2, v); mn2 = fminf(mn2, v); }
            }
        m1 = fmaxf(m1, __shfl_xor_sync(0xffffffffu, m1, 1));
        m1 = fmaxf(m1, __shfl_xor_sync(0xffffffffu, m1, 2));
        m2 = fmaxf(m2, __shfl_xor_sync(0xffffffffu, m2, 1));
        m2 = fmaxf(m2, __shfl_xor_sync(0xffffffffu, m2, 2));
        mn2 = fminf(mn2, __shfl_xor_sync(0xffffffffu, mn2, 1));
        mn2 = fminf(mn2, __shfl_xor_sync(0xffffffffu, mn2, 2));
        float s1 = 0.f, s2 = 0.f;
#pragma unroll
        for (int nt = 0; nt < NT; nt++)
#pragma unroll
            for (int e = 0; e < 2; e++) {
                int j = nt * 8 + c2 + e;
                float v = acc1[nt][half * 2 + e] + acc2[nt][half * 2 + e] * RINV + cb[j];
                if (j < 20) {
                    float ex = __expf(v - m1);
                    if (nt < 3) ecls[half][nt * 2 + e] = ex;
                    s1 += ex;
                } else {
                    s2 += __expf(v - m2);
                }
            }
        s1 += __shfl_xor_sync(0xffffffffu, s1, 1);
        s1 += __shfl_xor_sync(0xffffffffu, s1, 2);
        s2 += __shfl_xor_sync(0xffffffffu, s2, 1);
        s2 += __shfl_xor_sync(0xffffffffu, s2, 2);
        float pred = 1.0f / s1;
        float tau  = __expf(mn2 - m2) / s2;
        scl[half] = (pred >= tau + SMARGIN) ? pred : 0.0f;
    }
#pragma unroll
    for (int half = 0; half < 2; half++) {
        float* orow = out + (size_t)(row0 + half * 8) * 20;
#pragma unroll
        for (int nt = 0; nt < 3; nt++) {
            int j0 = nt * 8 + c2;
            if (j0 < 20)
                *(float2*)(orow + j0) = make_float2(ecls[half][nt * 2 + 0] * scl[half],
                                                    ecls[half][nt * 2 + 1] * scl[half]);
        }
    }
}

// ---------------------------------------------------------------------------
extern "C" void kernel_launch(void* const* d_in, const int* in_sizes, int n_in,
                              void* d_out, int out_size) {
    const float* x    = (const float*)d_in[0];
    const float* Wenc = (const float*)d_in[1];
    const float* benc = (const float*)d_in[2];
    const float* Wcls = (const float*)d_in[3];
    const float* bcls = (const float*)d_in[4];
    const float* Wfl  = (const float*)d_in[5];
    const float* bfl  = (const float*)d_in[6];
    float* out = (float*)d_out;
    int M = in_sizes[0] / KTOT;   // 16384

    static int smset = 0;
    if (!smset) {
        cudaFuncSetAttribute(mma_main_kernel,
                             cudaFuncAttributeMaxDynamicSharedMemorySize, 2 * BUFB);
        cudaFuncSetAttribute(prep_mma_kernel,
                             cudaFuncAttributeMaxDynamicSharedMemorySize, 2 * PBUF);
        smset = 1;
    }

    prep_mma_kernel<<<32 * NSPL, 128, 2 * PBUF>>>(Wenc, Wcls, Wfl);
    bsplit_bias_kernel<<<48, 256>>>(benc, Wcls, Wfl, bcls, bfl);
    mma_main_kernel<<<M / 128, 256, 2 * BUFB>>>(x, out);
}

// round 12
// speedup vs baseline: 1.0239x; 1.0114x over previous
#include <cuda_runtime.h>
#include <cuda_fp16.h>
#include <math.h>
#include <cstdint>

#define KTOT 2048
#define NJ   40
#define NT   5
#define NKC  128            // 2048/16 k-steps total
#define NBIAS 16
#define NSPL 8              // prep K-splits
#define SMARGIN 0.31f
#define RSCALE 2048.0f
#define RINV   (1.0f / 2048.0f)
#define XBYTES 34816u       // main: 128 rows * 272 B
#define BBYTES 10240u       // 640 uint2 hi + 640 uint2 lo per 64-k chunk
#define BUFB   (XBYTES + BBYTES)
#define PXB    17408u       // prep: 64 rows * 272 B
#define PBUF   (PXB + BBYTES)

// ---- device scratch -------------------------------------------------------
__device__ float g_c[NJ];
__device__ float g_cpart[NBIAS * NJ];
__device__ float g_part[NSPL * KTOT * NJ];
__device__ uint2 g_Wfh[NKC * NT * 32];   // Wp fragments fp16 hi
__device__ uint2 g_Wfl[NKC * NT * 32];   // Wp fragments fp16 residual*2048
__device__ uint2 g_Bfh[NKC * NT * 32];   // W12 fragments fp16 hi
__device__ uint2 g_Bfl[NKC * NT * 32];   // W12 fragments fp16 residual*2048

// ---- helpers --------------------------------------------------------------
__device__ __forceinline__ uint32_t smem_u32(const void* p) {
    uint32_t a;
    asm("{ .reg .u64 t; cvta.to.shared.u64 t, %1; cvt.u32.u64 %0, t; }" : "=r"(a) : "l"(p));
    return a;
}
__device__ __forceinline__ void cp_async16(uint32_t d, const void* s) {
    asm volatile("cp.async.cg.shared.global [%0], [%1], 16;" :: "r"(d), "l"(s));
}
__device__ __forceinline__ void cp_commit() { asm volatile("cp.async.commit_group;" ::: "memory"); }
__device__ __forceinline__ void cp_wait0()  { asm volatile("cp.async.wait_group 0;" ::: "memory"); }

#define MMA_F16(d, a0, a1, a2, a3, b0, b1)                                    \
    asm volatile("mma.sync.aligned.m16n8k16.row.col.f32.f16.f16.f32 "         \
                 "{%0,%1,%2,%3}, {%4,%5,%6,%7}, {%8,%9}, {%0,%1,%2,%3};\n"    \
                 : "+f"(d[0]), "+f"(d[1]), "+f"(d[2]), "+f"(d[3])             \
                 : "r"(a0), "r"(a1), "r"(a2), "r"(a3), "r"(b0), "r"(b1))

__device__ __forceinline__ void cvt_split_h(float2 v, unsigned& h, unsigned& l) {
    __half2 hh = __floats2half2_rn(v.x, v.y);
    float2 hf = __half22float2(hh);
    __half2 ll = __floats2half2_rn((v.x - hf.x) * RSCALE, (v.y - hf.y) * RSCALE);
    h = *reinterpret_cast<unsigned*>(&hh);
    l = *reinterpret_cast<unsigned*>(&ll);
}
__device__ __forceinline__ unsigned pack_h2(float a, float b) {
    __half2 h = __floats2half2_rn(a, b);
    return *reinterpret_cast<unsigned*>(&h);
}

// ---------------------------------------------------------------------------
// Kernel A: blocks 0..127 pack Wp=[Wcls|Wfl] into fp16 hi/lo MMA fragments;
//           blocks 128..143 bias partials; block 128 inits g_c raw biases.
// ---------------------------------------------------------------------------
__global__ __launch_bounds__(256)
void wfrag_bias_kernel(const float* __restrict__ Wcls, const float* __restrict__ Wfl,
                       const float* __restrict__ benc,
                       const float* __restrict__ bcls, const float* __restrict__ bfl) {
    int b = blockIdx.x;
    int tid = threadIdx.x;
    if (b < 128) {                       // one 16-row kc16 slab per block
        __shared__ float wp[16 * NJ];
        for (int i = tid; i < 16 * NJ; i += 256) {
            int m = i / NJ, n = i - (i / NJ) * NJ;
            int gm = b * 16 + m;
            wp[i] = (n < 20) ? Wcls[(size_t)gm * 20 + n] : Wfl[(size_t)gm * 20 + (n - 20)];
        }
        __syncthreads();
        if (tid < 160) {
            int lane = tid & 31, nt = tid >> 5;
            int m0 = (lane & 3) * 2, n = nt * 8 + (lane >> 2);
            float v[4], rr[4];
#pragma unroll
            for (int e = 0; e < 4; e++) {
                v[e] = wp[(m0 + (e >> 1) * 8 + (e & 1)) * NJ + n];
                __half h = __float2half_rn(v[e]);
                rr[e] = (v[e] - __half2float(h)) * RSCALE;
            }
            int gi = b * 160 + tid;
            g_Wfh[gi] = make_uint2(pack_h2(v[0], v[1]), pack_h2(v[2], v[3]));
            g_Wfl[gi] = make_uint2(pack_h2(rr[0], rr[1]), pack_h2(rr[2], rr[3]));
        }
        return;
    }
    // bias blocks
    __shared__ float sw[4][NJ];
    int bb = b - 128;
    if (tid >= 128) return;
    int k = bb * 128 + tid;
    int warp = tid >> 5, lane = tid & 31;
    float bv = benc[k];
    float w[NJ];
#pragma unroll
    for (int j4 = 0; j4 < 5; j4++) {
        float4 v = *(const float4*)(Wcls + (size_t)k * 20 + j4 * 4);
        w[j4*4+0] = v.x; w[j4*4+1] = v.y; w[j4*4+2] = v.z; w[j4*4+3] = v.w;
    }
#pragma unroll
    for (int j4 = 0; j4 < 5; j4++) {
        float4 v = *(const float4*)(Wfl + (size_t)k * 20 + j4 * 4);
        w[20+j4*4+0] = v.x; w[20+j4*4+1] = v.y; w[20+j4*4+2] = v.z; w[20+j4*4+3] = v.w;
    }
#pragma unroll
    for (int j = 0; j < NJ; j++) {
        float s = bv * w[j];
#pragma unroll
        for (int o = 16; o > 0; o >>= 1) s += __shfl_xor_sync(0xffffffffu, s, o);
        if (lane == 0) sw[warp][j] = s;
    }
    __syncthreads();
    if (tid < NJ) {
        g_cpart[bb * NJ + tid] = (sw[0][tid] + sw[1][tid]) + (sw[2][tid] + sw[3][tid]);
        if (bb == 0) g_c[tid] = (tid < 20) ? bcls[tid] : bfl[tid - 20];
    }
}

// ---------------------------------------------------------------------------
// Kernel B: prep GEMM  g_part[split] = W_enc @ Wp  using pre-packed fragments.
// grid 256 = 32 m-tiles (64 rows) x 8 K-splits, 128 threads, 4 chunks each.
// Structurally identical to the main kernel's inner loop.
// ---------------------------------------------------------------------------
__device__ __forceinline__ void prep_stage(uint32_t smb, int buf, int gchunk,
                                           const float* __restrict__ Wenc,
                                           int tilebase, int tid) {
    uint32_t xd = smb + (uint32_t)buf * PBUF;
#pragma unroll
    for (int it = 0; it < 8; it++) {
        int q = it * 128 + tid;               // 1024 float4 for 64 rows x 64 k
        int rw = q >> 4, c4 = q & 15;
        cp_async16(xd + (uint32_t)(rw * 272 + c4 * 16),
                   Wenc + (size_t)(tilebase + rw) * KTOT + gchunk * 64 + c4 * 4);
    }
    uint32_t bd = xd + PXB;
    const char* srcH = (const char*)(g_Wfh + (size_t)gchunk * 640);
    const char* srcL = (const char*)(g_Wfl + (size_t)gchunk * 640);
#pragma unroll
    for (int it = 0; it < 5; it++) {
        int q = it * 128 + tid;               // 640 x 16B
        if (q < 320)      cp_async16(bd + (uint32_t)q * 16, srcH + q * 16);
        else              cp_async16(bd + 5120u + (uint32_t)(q - 320) * 16, srcL + (q - 320) * 16);
    }
}

__global__ __launch_bounds__(128)
void prep_mma_kernel(const float* __restrict__ Wenc) {
    extern __shared__ char sm[];
    const int tid = threadIdx.x;
    const int warp = tid >> 5, lane = tid & 31;
    const int c2 = (lane & 3) * 2;
    const int tile = blockIdx.x & 31, split = blockIdx.x >> 5;
    const int tilebase = tile * 64;
    const int chunk0 = split * 4;             // 4 chunks of 64 k per split

    const uint32_t smb = smem_u32(sm);
    prep_stage(smb, 0, chunk0, Wenc, tilebase, tid);
    cp_commit(); cp_wait0();
    __syncthreads();

    float acc1[NT][4], acc2[NT][4];
#pragma unroll
    for (int nt = 0; nt < NT; nt++)
#pragma unroll
        for (int e = 0; e < 4; e++) { acc1[nt][e] = 0.f; acc2[nt][e] = 0.f; }

    const uint32_t xoff = (uint32_t)((warp * 16 + (lane >> 2)) * 272 + c2 * 4);

    for (int c = 0; c < 4; c++) {
        int buf = c & 1;
        if (c + 1 < 4) { prep_stage(smb, buf ^ 1, chunk0 + c + 1, Wenc, tilebase, tid); cp_commit(); }
        uint32_t base = smb + (uint32_t)buf * PBUF;
        uint32_t xa = base + xoff;
        uint32_t ba = base + PXB + (uint32_t)lane * 8;
#pragma unroll
        for (int s = 0; s < 4; s++) {
            float2 v00, v10, v01, v11;
            asm("ld.shared.v2.f32 {%0, %1}, [%2];" : "=f"(v00.x), "=f"(v00.y) : "r"(xa + s * 64));
            asm("ld.shared.v2.f32 {%0, %1}, [%2];" : "=f"(v10.x), "=f"(v10.y) : "r"(xa + s * 64 + 8 * 272));
            asm("ld.shared.v2.f32 {%0, %1}, [%2];" : "=f"(v01.x), "=f"(v01.y) : "r"(xa + s * 64 + 32));
            asm("ld.shared.v2.f32 {%0, %1}, [%2];" : "=f"(v11.x), "=f"(v11.y) : "r"(xa + s * 64 + 32 + 8 * 272));
            unsigned ah0, ah1, ah2, ah3, al0, al1, al2, al3;
            cvt_split_h(v00, ah0, al0);
            cvt_split_h(v10, ah1, al1);
            cvt_split_h(v01, ah2, al2);
            cvt_split_h(v11, ah3, al3);
#pragma unroll
            for (int nt = 0; nt < NT; nt++) {
                uint2 wh, wl;
                uint32_t fo = (uint32_t)((s * NT + nt) * 32) * 8;
                asm("ld.shared.v2.u32 {%0, %1}, [%2];" : "=r"(wh.x), "=r"(wh.y) : "r"(ba + fo));
                asm("ld.shared.v2.u32 {%0, %1}, [%2];" : "=r"(wl.x), "=r"(wl.y) : "r"(ba + fo + 5120));
                MMA_F16(acc1[nt], ah0, ah1, ah2, ah3, wh.x, wh.y);
                MMA_F16(acc2[nt], al0, al1, al2, al3, wh.x, wh.y);
                MMA_F16(acc2[nt], ah0, ah1, ah2, ah3, wl.x, wl.y);
            }
        }
        if (c + 1 < 4) cp_wait0();
        __syncthreads();
    }

    int krow = tilebase + warp * 16 + (lane >> 2);
#pragma unroll
    for (int nt = 0; nt < NT; nt++) {
        float* p0 = g_part + ((size_t)split * KTOT + krow) * NJ + nt * 8 + c2;
        float* p1 = p0 + 8 * NJ;
        *(float2*)p0 = make_float2(acc1[nt][0] + acc2[nt][0] * RINV,
                                   acc1[nt][1] + acc2[nt][1] * RINV);
        *(float2*)p1 = make_float2(acc1[nt][2] + acc2[nt][2] * RINV,
                                   acc1[nt][3] + acc2[nt][3] * RINV);
    }
}

// ---------------------------------------------------------------------------
// Kernel C: coalesced reduce of 8 partial slabs -> W12 fragment pack.
// ---------------------------------------------------------------------------
__global__ __launch_bounds__(256)
void bsplit_kernel() {
    int b = blockIdx.x;                       // 0..31, 64-row W12 slab each
    int tid = threadIdx.x;
    __shared__ float w12[64 * NJ];            // 2560 floats
    float r[10];
#pragma unroll
    for (int i = 0; i < 10; i++) r[i] = 0.f;
    size_t cellbase = (size_t)b * 2560;
#pragma unroll
    for (int s = 0; s < NSPL; s++) {
        const float* src = g_part + (size_t)s * (KTOT * NJ) + cellbase;
#pragma unroll
        for (int i = 0; i < 10; i++) r[i] += src[tid + i * 256];
    }
#pragma unroll
    for (int i = 0; i < 10; i++) w12[tid + i * 256] = r[i];
    __syncthreads();
#pragma unroll
    for (int i = 0; i < 3; i++) {
        int f = tid + i * 256;
        if (f < 640) {
            int kc16l = f / 160;
            int rem = f - kc16l * 160;
            int nt = rem >> 5, lane = rem & 31;
            int k0l = kc16l * 16 + (lane & 3) * 2;
            int n = nt * 8 + (lane >> 2);
            float v[4], rr[4];
#pragma unroll
            for (int e = 0; e < 4; e++) {
                v[e] = w12[(k0l + (e >> 1) * 8 + (e & 1)) * NJ + n];
                __half h = __float2half_rn(v[e]);
                rr[e] = (v[e] - __half2float(h)) * RSCALE;
            }
            int gi = b * 640 + f;
            g_Bfh[gi] = make_uint2(pack_h2(v[0], v[1]), pack_h2(v[2], v[3]));
            g_Bfl[gi] = make_uint2(pack_h2(rr[0], rr[1]), pack_h2(rr[2], rr[3]));
        }
    }
}

// ---------------------------------------------------------------------------
// Main kernel (UNCHANGED, validated R9/R10): 128 rows x 40 cols per CTA,
// fp16 3-term mma.sync, double-buffered cp.async, fused dual-softmax epilogue.
// ---------------------------------------------------------------------------
__device__ __forceinline__ void stage_chunk(uint32_t smb, int buf, int c,
                                            const float* __restrict__ x,
                                            size_t growbase, int tid) {
    uint32_t xd = smb + (uint32_t)buf * BUFB;
#pragma unroll
    for (int it = 0; it < 8; it++) {
        int q = it * 256 + tid;
        int rw = q >> 4, c4 = q & 15;
        cp_async16(xd + (uint32_t)(rw * 272 + c4 * 16),
                   x + (growbase + rw) * KTOT + c * 64 + c4 * 4);
    }
    uint32_t bd = xd + XBYTES;
    const char* srcH = (const char*)(g_Bfh + (size_t)c * 640);
    const char* srcL = (const char*)(g_Bfl + (size_t)c * 640);
#pragma unroll
    for (int it = 0; it < 3; it++) {
        int q = it * 256 + tid;
        if (q < 320)      cp_async16(bd + (uint32_t)q * 16, srcH + q * 16);
        else if (q < 640) cp_async16(bd + 5120u + (uint32_t)(q - 320) * 16, srcL + (q - 320) * 16);
    }
}

__global__ __launch_bounds__(256, 1)
void mma_main_kernel(const float* __restrict__ x, float* __restrict__ out) {
    extern __shared__ char sm[];
    __shared__ float cb[NJ];
    const int tid = threadIdx.x;
    const int warp = tid >> 5, lane = tid & 31;
    const int c2 = (lane & 3) * 2;
    const size_t growbase = (size_t)blockIdx.x * 128;

    if (tid < NJ) {
        float s = g_c[tid];
#pragma unroll
        for (int p = 0; p < NBIAS; p++) s += g_cpart[p * NJ + tid];
        cb[tid] = s;
    }

    const uint32_t smb = smem_u32(sm);
    stage_chunk(smb, 0, 0, x, growbase, tid);
    cp_commit(); cp_wait0();
    __syncthreads();

    float acc1[NT][4], acc2[NT][4];
#pragma unroll
    for (int nt = 0; nt < NT; nt++)
#pragma unroll
        for (int e = 0; e < 4; e++) { acc1[nt][e] = 0.f; acc2[nt][e] = 0.f; }

    const uint32_t xoff = (uint32_t)((warp * 16 + (lane >> 2)) * 272 + c2 * 4);

    for (int c = 0; c < 32; c++) {
        int buf = c & 1;
        if (c + 1 < 32) { stage_chunk(smb, buf ^ 1, c + 1, x, growbase, tid); cp_commit(); }
        uint32_t base = smb + (uint32_t)buf * BUFB;
        uint32_t xa = base + xoff;
        uint32_t ba = base + XBYTES + (uint32_t)lane * 8;
#pragma unroll
        for (int s = 0; s < 4; s++) {
            float2 v00, v10, v01, v11;
            asm("ld.shared.v2.f32 {%0, %1}, [%2];" : "=f"(v00.x), "=f"(v00.y) : "r"(xa + s * 64));
            asm("ld.shared.v2.f32 {%0, %1}, [%2];" : "=f"(v10.x), "=f"(v10.y) : "r"(xa + s * 64 + 8 * 272));
            asm("ld.shared.v2.f32 {%0, %1}, [%2];" : "=f"(v01.x), "=f"(v01.y) : "r"(xa + s * 64 + 32));
            asm("ld.shared.v2.f32 {%0, %1}, [%2];" : "=f"(v11.x), "=f"(v11.y) : "r"(xa + s * 64 + 32 + 8 * 272));
            unsigned ah0, ah1, ah2, ah3, al0, al1, al2, al3;
            cvt_split_h(v00, ah0, al0);
            cvt_split_h(v10, ah1, al1);
            cvt_split_h(v01, ah2, al2);
            cvt_split_h(v11, ah3, al3);
#pragma unroll
            for (int nt = 0; nt < NT; nt++) {
                uint2 wh, wl;
                uint32_t fo = (uint32_t)((s * NT + nt) * 32) * 8;
                asm("ld.shared.v2.u32 {%0, %1}, [%2];" : "=r"(wh.x), "=r"(wh.y) : "r"(ba + fo));
                asm("ld.shared.v2.u32 {%0, %1}, [%2];" : "=r"(wl.x), "=r"(wl.y) : "r"(ba + fo + 5120));
                MMA_F16(acc1[nt], ah0, ah1, ah2, ah3, wh.x, wh.y);
                MMA_F16(acc2[nt], al0, al1, al2, al3, wh.x, wh.y);
                MMA_F16(acc2[nt], ah0, ah1, ah2, ah3, wl.x, wl.y);
            }
        }
        if (c + 1 < 32) cp_wait0();
        __syncthreads();
    }

    // ---- epilogue: combine scales, dual softmax + threshold ---------------
    int row0 = (int)growbase + warp * 16 + (lane >> 2);
    float scl[2];
    float ecls[2][6];
#pragma unroll
    for (int half = 0; half < 2; half++) {
        float m1 = -1e30f, m2 = -1e30f, mn2 = 1e30f;
#pragma unroll
        for (int nt = 0; nt < NT; nt++)
#pragma unroll
            for (int e = 0; e < 2; e++) {
                int j = nt * 8 + c2 + e;
                float v = acc1[nt][half * 2 + e] + acc2[nt][half * 2 + e] * RINV + cb[j];
                if (j < 20) m1 = fmaxf(m1, v);
                else { m2 = fmaxf(m2, v); mn2 = fminf(mn2, v); }
            }
        m1 = fmaxf(m1, __shfl_xor_sync(0xffffffffu, m1, 1));
        m1 = fmaxf(m1, __shfl_xor_sync(0xffffffffu, m1, 2));
        m2 = fmaxf(m2, __shfl_xor_sync(0xffffffffu, m2, 1));
        m2 = fmaxf(m2, __shfl_xor_sync(0xffffffffu, m2, 2));
        mn2 = fminf(mn2, __shfl_xor_sync(0xffffffffu, mn2, 1));
        mn2 = fminf(mn2, __shfl_xor_sync(0xffffffffu, mn2, 2));
        float s1 = 0.f, s2 = 0.f;
#pragma unroll
        for (int nt = 0; nt < NT; nt++)
#pragma unroll
            for (int e = 0; e < 2; e++) {
                int j = nt * 8 + c2 + e;
                float v = acc1[nt][half * 2 + e] + acc2[nt][half * 2 + e] * RINV + cb[j];
                if (j < 20) {
                    float ex = __expf(v - m1);
                    if (nt < 3) ecls[half][nt * 2 + e] = ex;
                    s1 += ex;
                } else {
                    s2 += __expf(v - m2);
                }
            }
        s1 += __shfl_xor_sync(0xffffffffu, s1, 1);
        s1 += __shfl_xor_sync(0xffffffffu, s1, 2);
        s2 += __shfl_xor_sync(0xffffffffu, s2, 1);
        s2 += __shfl_xor_sync(0xffffffffu, s2, 2);
        float pred = 1.0f / s1;
        float tau  = __expf(mn2 - m2) / s2;
        scl[half] = (pred >= tau + SMARGIN) ? pred : 0.0f;
    }
#pragma unroll
    for (int half = 0; half < 2; half++) {
        float* orow = out + (size_t)(row0 + half * 8) * 20;
#pragma unroll
        for (int nt = 0; nt < 3; nt++) {
            int j0 = nt * 8 + c2;
            if (j0 < 20)
                *(float2*)(orow + j0) = make_float2(ecls[half][nt * 2 + 0] * scl[half],
                                                    ecls[half][nt * 2 + 1] * scl[half]);
        }
    }
}

// ---------------------------------------------------------------------------
extern "C" void kernel_launch(void* const* d_in, const int* in_sizes, int n_in,
                              void* d_out, int out_size) {
    const float* x    = (const float*)d_in[0];
    const float* Wenc = (const float*)d_in[1];
    const float* benc = (const float*)d_in[2];
    const float* Wcls = (const float*)d_in[3];
    const float* bcls = (const float*)d_in[4];
    const float* Wfl  = (const float*)d_in[5];
    const float* bfl  = (const float*)d_in[6];
    float* out = (float*)d_out;
    int M = in_sizes[0] / KTOT;   // 16384

    static int smset = 0;
    if (!smset) {
        cudaFuncSetAttribute(mma_main_kernel,
                             cudaFuncAttributeMaxDynamicSharedMemorySize, 2 * BUFB);
        cudaFuncSetAttribute(prep_mma_kernel,
                             cudaFuncAttributeMaxDynamicSharedMemorySize, 2 * PBUF);
        smset = 1;
    }

    wfrag_bias_kernel<<<144, 256>>>(Wcls, Wfl, benc, bcls, bfl);
    prep_mma_kernel<<<32 * NSPL, 128, 2 * PBUF>>>(Wenc);
    bsplit_kernel<<<32, 256>>>();
    mma_main_kernel<<<M / 128, 256, 2 * BUFB>>>(x, out);
}

// round 13
// speedup vs baseline: 1.0468x; 1.0223x over previous
#include <cuda_runtime.h>
#include <cuda_fp16.h>
#include <math.h>
#include <cstdint>

#define KTOT 2048
#define NJ   40
#define NT   5
#define NKC  128            // 2048/16 k-steps total
#define NBIAS 16
#define NSPL 8              // prep K-splits
#define SMARGIN 0.31f
#define RSCALE 2048.0f
#define RINV   (1.0f / 2048.0f)
#define PXB    17408u       // 64 rows * 272 B
#define BBYTES 10240u       // 640 uint2 hi + 640 uint2 lo per 64-k chunk
#define PBUF   (PXB + BBYTES)

// ---- device scratch -------------------------------------------------------
__device__ float g_c[NJ];
__device__ float g_cpart[NBIAS * NJ];
__device__ float g_part[NSPL * KTOT * NJ];
__device__ uint2 g_Wfh[NKC * NT * 32];   // Wp fragments fp16 hi
__device__ uint2 g_Wfl[NKC * NT * 32];   // Wp fragments fp16 residual*2048
__device__ uint2 g_Bfh[NKC * NT * 32];   // W12 fragments fp16 hi
__device__ uint2 g_Bfl[NKC * NT * 32];   // W12 fragments fp16 residual*2048

// ---- helpers --------------------------------------------------------------
__device__ __forceinline__ uint32_t smem_u32(const void* p) {
    uint32_t a;
    asm("{ .reg .u64 t; cvta.to.shared.u64 t, %1; cvt.u32.u64 %0, t; }" : "=r"(a) : "l"(p));
    return a;
}
__device__ __forceinline__ void cp_async16(uint32_t d, const void* s) {
    asm volatile("cp.async.cg.shared.global [%0], [%1], 16;" :: "r"(d), "l"(s));
}
__device__ __forceinline__ void cp_commit() { asm volatile("cp.async.commit_group;" ::: "memory"); }
__device__ __forceinline__ void cp_wait0()  { asm volatile("cp.async.wait_group 0;" ::: "memory"); }

#define MMA_F16(d, a0, a1, a2, a3, b0, b1)                                    \
    asm volatile("mma.sync.aligned.m16n8k16.row.col.f32.f16.f16.f32 "         \
                 "{%0,%1,%2,%3}, {%4,%5,%6,%7}, {%8,%9}, {%0,%1,%2,%3};\n"    \
                 : "+f"(d[0]), "+f"(d[1]), "+f"(d[2]), "+f"(d[3])             \
                 : "r"(a0), "r"(a1), "r"(a2), "r"(a3), "r"(b0), "r"(b1))

__device__ __forceinline__ void cvt_split_h(float2 v, unsigned& h, unsigned& l) {
    __half2 hh = __floats2half2_rn(v.x, v.y);
    float2 hf = __half22float2(hh);
    __half2 ll = __floats2half2_rn((v.x - hf.x) * RSCALE, (v.y - hf.y) * RSCALE);
    h = *reinterpret_cast<unsigned*>(&hh);
    l = *reinterpret_cast<unsigned*>(&ll);
}
__device__ __forceinline__ unsigned pack_h2(float a, float b) {
    __half2 h = __floats2half2_rn(a, b);
    return *reinterpret_cast<unsigned*>(&h);
}

// ---------------------------------------------------------------------------
// Kernel A: blocks 0..127 pack Wp=[Wcls|Wfl] into fp16 hi/lo MMA fragments;
//           blocks 128..143 bias partials; block 128 inits g_c raw biases.
// ---------------------------------------------------------------------------
__global__ __launch_bounds__(256)
void wfrag_bias_kernel(const float* __restrict__ Wcls, const float* __restrict__ Wfl,
                       const float* __restrict__ benc,
                       const float* __restrict__ bcls, const float* __restrict__ bfl) {
    int b = blockIdx.x;
    int tid = threadIdx.x;
    if (b < 128) {                       // one 16-row kc16 slab per block
        __shared__ float wp[16 * NJ];
        for (int i = tid; i < 16 * NJ; i += 256) {
            int m = i / NJ, n = i - (i / NJ) * NJ;
            int gm = b * 16 + m;
            wp[i] = (n < 20) ? Wcls[(size_t)gm * 20 + n] : Wfl[(size_t)gm * 20 + (n - 20)];
        }
        __syncthreads();
        if (tid < 160) {
            int lane = tid & 31, nt = tid >> 5;
            int m0 = (lane & 3) * 2, n = nt * 8 + (lane >> 2);
            float v[4], rr[4];
#pragma unroll
            for (int e = 0; e < 4; e++) {
                v[e] = wp[(m0 + (e >> 1) * 8 + (e & 1)) * NJ + n];
                __half h = __float2half_rn(v[e]);
                rr[e] = (v[e] - __half2float(h)) * RSCALE;
            }
            int gi = b * 160 + tid;
            g_Wfh[gi] = make_uint2(pack_h2(v[0], v[1]), pack_h2(v[2], v[3]));
            g_Wfl[gi] = make_uint2(pack_h2(rr[0], rr[1]), pack_h2(rr[2], rr[3]));
        }
        return;
    }
    // bias blocks
    __shared__ float sw[4][NJ];
    int bb = b - 128;
    if (tid >= 128) return;
    int k = bb * 128 + tid;
    int warp = tid >> 5, lane = tid & 31;
    float bv = benc[k];
    float w[NJ];
#pragma unroll
    for (int j4 = 0; j4 < 5; j4++) {
        float4 v = *(const float4*)(Wcls + (size_t)k * 20 + j4 * 4);
        w[j4*4+0] = v.x; w[j4*4+1] = v.y; w[j4*4+2] = v.z; w[j4*4+3] = v.w;
    }
#pragma unroll
    for (int j4 = 0; j4 < 5; j4++) {
        float4 v = *(const float4*)(Wfl + (size_t)k * 20 + j4 * 4);
        w[20+j4*4+0] = v.x; w[20+j4*4+1] = v.y; w[20+j4*4+2] = v.z; w[20+j4*4+3] = v.w;
    }
#pragma unroll
    for (int j = 0; j < NJ; j++) {
        float s = bv * w[j];
#pragma unroll
        for (int o = 16; o > 0; o >>= 1) s += __shfl_xor_sync(0xffffffffu, s, o);
        if (lane == 0) sw[warp][j] = s;
    }
    __syncthreads();
    if (tid < NJ) {
        g_cpart[bb * NJ + tid] = (sw[0][tid] + sw[1][tid]) + (sw[2][tid] + sw[3][tid]);
        if (bb == 0) g_c[tid] = (tid < 20) ? bcls[tid] : bfl[tid - 20];
    }
}

// ---------------------------------------------------------------------------
// Shared 64-row staging helper: x slab (64x64 fp32) + fragment chunk (hi/lo)
// ---------------------------------------------------------------------------
__device__ __forceinline__ void stage64(uint32_t smb, int buf, int gchunk,
                                        const float* __restrict__ src, size_t rowbase,
                                        const uint2* __restrict__ fh,
                                        const uint2* __restrict__ fl, int tid) {
    uint32_t xd = smb + (uint32_t)buf * PBUF;
#pragma unroll
    for (int it = 0; it < 8; it++) {
        int q = it * 128 + tid;               // 1024 float4 = 64 rows x 16 seg
        int rw = q >> 4, c4 = q & 15;
        cp_async16(xd + (uint32_t)(rw * 272 + c4 * 16),
                   src + (rowbase + rw) * KTOT + gchunk * 64 + c4 * 4);
    }
    uint32_t bd = xd + PXB;
    const char* srcH = (const char*)(fh + (size_t)gchunk * 640);
    const char* srcL = (const char*)(fl + (size_t)gchunk * 640);
#pragma unroll
    for (int it = 0; it < 5; it++) {
        int q = it * 128 + tid;               // 640 x 16B
        if (q < 320) cp_async16(bd + (uint32_t)q * 16, srcH + q * 16);
        else         cp_async16(bd + 5120u + (uint32_t)(q - 320) * 16, srcL + (q - 320) * 16);
    }
}

// ---------------------------------------------------------------------------
// Kernel B: prep GEMM  g_part[split] = W_enc @ Wp  using pre-packed fragments.
// grid 256 = 32 m-tiles (64 rows) x 8 K-splits, 128 threads, 4 chunks each.
// ---------------------------------------------------------------------------
__global__ __launch_bounds__(128)
void prep_mma_kernel(const float* __restrict__ Wenc) {
    extern __shared__ char sm[];
    const int tid = threadIdx.x;
    const int warp = tid >> 5, lane = tid & 31;
    const int c2 = (lane & 3) * 2;
    const int tile = blockIdx.x & 31, split = blockIdx.x >> 5;
    const size_t tilebase = (size_t)tile * 64;
    const int chunk0 = split * 4;

    const uint32_t smb = smem_u32(sm);
    stage64(smb, 0, chunk0, Wenc, tilebase, g_Wfh, g_Wfl, tid);
    cp_commit(); cp_wait0();
    __syncthreads();

    float acc1[NT][4], acc2[NT][4];
#pragma unroll
    for (int nt = 0; nt < NT; nt++)
#pragma unroll
        for (int e = 0; e < 4; e++) { acc1[nt][e] = 0.f; acc2[nt][e] = 0.f; }

    const uint32_t xoff = (uint32_t)((warp * 16 + (lane >> 2)) * 272 + c2 * 4);

    for (int c = 0; c < 4; c++) {
        int buf = c & 1;
        if (c + 1 < 4) { stage64(smb, buf ^ 1, chunk0 + c + 1, Wenc, tilebase, g_Wfh, g_Wfl, tid); cp_commit(); }
        uint32_t base = smb + (uint32_t)buf * PBUF;
        uint32_t xa = base + xoff;
        uint32_t ba = base + PXB + (uint32_t)lane * 8;
#pragma unroll
        for (int s = 0; s < 4; s++) {
            float2 v00, v10, v01, v11;
            asm("ld.shared.v2.f32 {%0, %1}, [%2];" : "=f"(v00.x), "=f"(v00.y) : "r"(xa + s * 64));
            asm("ld.shared.v2.f32 {%0, %1}, [%2];" : "=f"(v10.x), "=f"(v10.y) : "r"(xa + s * 64 + 8 * 272));
            asm("ld.shared.v2.f32 {%0, %1}, [%2];" : "=f"(v01.x), "=f"(v01.y) : "r"(xa + s * 64 + 32));
            asm("ld.shared.v2.f32 {%0, %1}, [%2];" : "=f"(v11.x), "=f"(v11.y) : "r"(xa + s * 64 + 32 + 8 * 272));
            unsigned ah0, ah1, ah2, ah3, al0, al1, al2, al3;
            cvt_split_h(v00, ah0, al0);
            cvt_split_h(v10, ah1, al1);
            cvt_split_h(v01, ah2, al2);
            cvt_split_h(v11, ah3, al3);
#pragma unroll
            for (int nt = 0; nt < NT; nt++) {
                uint2 wh, wl;
                uint32_t fo = (uint32_t)((s * NT + nt) * 32) * 8;
                asm("ld.shared.v2.u32 {%0, %1}, [%2];" : "=r"(wh.x), "=r"(wh.y) : "r"(ba + fo));
                asm("ld.shared.v2.u32 {%0, %1}, [%2];" : "=r"(wl.x), "=r"(wl.y) : "r"(ba + fo + 5120));
                MMA_F16(acc1[nt], ah0, ah1, ah2, ah3, wh.x, wh.y);
                MMA_F16(acc2[nt], al0, al1, al2, al3, wh.x, wh.y);
                MMA_F16(acc2[nt], ah0, ah1, ah2, ah3, wl.x, wl.y);
            }
        }
        if (c + 1 < 4) cp_wait0();
        __syncthreads();
    }

    int krow = (int)tilebase + warp * 16 + (lane >> 2);
#pragma unroll
    for (int nt = 0; nt < NT; nt++) {
        float* p0 = g_part + ((size_t)split * KTOT + krow) * NJ + nt * 8 + c2;
        float* p1 = p0 + 8 * NJ;
        *(float2*)p0 = make_float2(acc1[nt][0] + acc2[nt][0] * RINV,
                                   acc1[nt][1] + acc2[nt][1] * RINV);
        *(float2*)p1 = make_float2(acc1[nt][2] + acc2[nt][2] * RINV,
                                   acc1[nt][3] + acc2[nt][3] * RINV);
    }
}

// ---------------------------------------------------------------------------
// Kernel C: coalesced reduce of 8 partial slabs -> W12 fragment pack.
// ---------------------------------------------------------------------------
__global__ __launch_bounds__(256)
void bsplit_kernel() {
    int b = blockIdx.x;                       // 0..31, 64-row W12 slab each
    int tid = threadIdx.x;
    __shared__ float w12[64 * NJ];
    float r[10];
#pragma unroll
    for (int i = 0; i < 10; i++) r[i] = 0.f;
    size_t cellbase = (size_t)b * 2560;
#pragma unroll
    for (int s = 0; s < NSPL; s++) {
        const float* src = g_part + (size_t)s * (KTOT * NJ) + cellbase;
#pragma unroll
        for (int i = 0; i < 10; i++) r[i] += src[tid + i * 256];
    }
#pragma unroll
    for (int i = 0; i < 10; i++) w12[tid + i * 256] = r[i];
    __syncthreads();
#pragma unroll
    for (int i = 0; i < 3; i++) {
        int f = tid + i * 256;
        if (f < 640) {
            int kc16l = f / 160;
            int rem = f - kc16l * 160;
            int nt = rem >> 5, lane = rem & 31;
            int k0l = kc16l * 16 + (lane & 3) * 2;
            int n = nt * 8 + (lane >> 2);
            float v[4], rr[4];
#pragma unroll
            for (int e = 0; e < 4; e++) {
                v[e] = w12[(k0l + (e >> 1) * 8 + (e & 1)) * NJ + n];
                __half h = __float2half_rn(v[e]);
                rr[e] = (v[e] - __half2float(h)) * RSCALE;
            }
            int gi = b * 640 + f;
            g_Bfh[gi] = make_uint2(pack_h2(v[0], v[1]), pack_h2(v[2], v[3]));
            g_Bfl[gi] = make_uint2(pack_h2(rr[0], rr[1]), pack_h2(rr[2], rr[3]));
        }
    }
}

// ---------------------------------------------------------------------------
// Main kernel: NOW 64 rows / 128 threads / grid 256 -> 4 CTAs/SM (occ fix).
// Inner loop identical per warp to the validated 128-row version.
// ---------------------------------------------------------------------------
__global__ __launch_bounds__(128)
void mma_main_kernel(const float* __restrict__ x, float* __restrict__ out) {
    extern __shared__ char sm[];
    __shared__ float cb[NJ];
    const int tid = threadIdx.x;
    const int warp = tid >> 5, lane = tid & 31;
    const int c2 = (lane & 3) * 2;
    const size_t growbase = (size_t)blockIdx.x * 64;

    if (tid < NJ) {
        float s = g_c[tid];
#pragma unroll
        for (int p = 0; p < NBIAS; p++) s += g_cpart[p * NJ + tid];
        cb[tid] = s;
    }

    const uint32_t smb = smem_u32(sm);
    stage64(smb, 0, 0, x, growbase, g_Bfh, g_Bfl, tid);
    cp_commit(); cp_wait0();
    __syncthreads();

    float acc1[NT][4], acc2[NT][4];
#pragma unroll
    for (int nt = 0; nt < NT; nt++)
#pragma unroll
        for (int e = 0; e < 4; e++) { acc1[nt][e] = 0.f; acc2[nt][e] = 0.f; }

    const uint32_t xoff = (uint32_t)((warp * 16 + (lane >> 2)) * 272 + c2 * 4);

    for (int c = 0; c < 32; c++) {
        int buf = c & 1;
        if (c + 1 < 32) { stage64(smb, buf ^ 1, c + 1, x, growbase, g_Bfh, g_Bfl, tid); cp_commit(); }
        uint32_t base = smb + (uint32_t)buf * PBUF;
        uint32_t xa = base + xoff;
        uint32_t ba = base + PXB + (uint32_t)lane * 8;
#pragma unroll
        for (int s = 0; s < 4; s++) {
            float2 v00, v10, v01, v11;
            asm("ld.shared.v2.f32 {%0, %1}, [%2];" : "=f"(v00.x), "=f"(v00.y) : "r"(xa + s * 64));
            asm("ld.shared.v2.f32 {%0, %1}, [%2];" : "=f"(v10.x), "=f"(v10.y) : "r"(xa + s * 64 + 8 * 272));
            asm("ld.shared.v2.f32 {%0, %1}, [%2];" : "=f"(v01.x), "=f"(v01.y) : "r"(xa + s * 64 + 32));
            asm("ld.shared.v2.f32 {%0, %1}, [%2];" : "=f"(v11.x), "=f"(v11.y) : "r"(xa + s * 64 + 32 + 8 * 272));
            unsigned ah0, ah1, ah2, ah3, al0, al1, al2, al3;
            cvt_split_h(v00, ah0, al0);
            cvt_split_h(v10, ah1, al1);
            cvt_split_h(v01, ah2, al2);
            cvt_split_h(v11, ah3, al3);
#pragma unroll
            for (int nt = 0; nt < NT; nt++) {
                uint2 wh, wl;
                uint32_t fo = (uint32_t)((s * NT + nt) * 32) * 8;
                asm("ld.shared.v2.u32 {%0, %1}, [%2];" : "=r"(wh.x), "=r"(wh.y) : "r"(ba + fo));
                asm("ld.shared.v2.u32 {%0, %1}, [%2];" : "=r"(wl.x), "=r"(wl.y) : "r"(ba + fo + 5120));
                MMA_F16(acc1[nt], ah0, ah1, ah2, ah3, wh.x, wh.y);
                MMA_F16(acc2[nt], al0, al1, al2, al3, wh.x, wh.y);
                MMA_F16(acc2[nt], ah0, ah1, ah2, ah3, wl.x, wl.y);
            }
        }
        if (c + 1 < 32) cp_wait0();
        __syncthreads();
    }

    // ---- epilogue: combine scales, dual softmax + threshold ---------------
    int row0 = (int)growbase + warp * 16 + (lane >> 2);
    float scl[2];
    float ecls[2][6];
#pragma unroll
    for (int half = 0; half < 2; half++) {
        float m1 = -1e30f, m2 = -1e30f, mn2 = 1e30f;
#pragma unroll
        for (int nt = 0; nt < NT; nt++)
#pragma unroll
            for (int e = 0; e < 2; e++) {
                int j = nt * 8 + c2 + e;
                float v = acc1[nt][half * 2 + e] + acc2[nt][half * 2 + e] * RINV + cb[j];
                if (j < 20) m1 = fmaxf(m1, v);
                else { m2 = fmaxf(m2, v); mn2 = fminf(mn2, v); }
            }
        m1 = fmaxf(m1, __shfl_xor_sync(0xffffffffu, m1, 1));
        m1 = fmaxf(m1, __shfl_xor_sync(0xffffffffu, m1, 2));
        m2 = fmaxf(m2, __shfl_xor_sync(0xffffffffu, m2, 1));
        m2 = fmaxf(m2, __shfl_xor_sync(0xffffffffu, m2, 2));
        mn2 = fminf(mn2, __shfl_xor_sync(0xffffffffu, mn2, 1));
        mn2 = fminf(mn2, __shfl_xor_sync(0xffffffffu, mn2, 2));
        float s1 = 0.f, s2 = 0.f;
#pragma unroll
        for (int nt = 0; nt < NT; nt++)
#pragma unroll
            for (int e = 0; e < 2; e++) {
                int j = nt * 8 + c2 + e;
                float v = acc1[nt][half * 2 + e] + acc2[nt][half * 2 + e] * RINV + cb[j];
                if (j < 20) {
                    float ex = __expf(v - m1);
                    if (nt < 3) ecls[half][nt * 2 + e] = ex;
                    s1 += ex;
                } else {
                    s2 += __expf(v - m2);
                }
            }
        s1 += __shfl_xor_sync(0xffffffffu, s1, 1);
        s1 += __shfl_xor_sync(0xffffffffu, s1, 2);
        s2 += __shfl_xor_sync(0xffffffffu, s2, 1);
        s2 += __shfl_xor_sync(0xffffffffu, s2, 2);
        float pred = 1.0f / s1;
        float tau  = __expf(mn2 - m2) / s2;
        scl[half] = (pred >= tau + SMARGIN) ? pred : 0.0f;
    }
#pragma unroll
    for (int half = 0; half < 2; half++) {
        float* orow = out + (size_t)(row0 + half * 8) * 20;
#pragma unroll
        for (int nt = 0; nt < 3; nt++) {
            int j0 = nt * 8 + c2;
            if (j0 < 20)
                *(float2*)(orow + j0) = make_float2(ecls[half][nt * 2 + 0] * scl[half],
                                                    ecls[half][nt * 2 + 1] * scl[half]);
        }
    }
}

// ---------------------------------------------------------------------------
extern "C" void kernel_launch(void* const* d_in, const int* in_sizes, int n_in,
                              void* d_out, int out_size) {
    const float* x    = (const float*)d_in[0];
    const float* Wenc = (const float*)d_in[1];
    const float* benc = (const float*)d_in[2];
    const float* Wcls = (const float*)d_in[3];
    const float* bcls = (const float*)d_in[4];
    const float* Wfl  = (const float*)d_in[5];
    const float* bfl  = (const float*)d_in[6];
    float* out = (float*)d_out;
    int M = in_sizes[0] / KTOT;   // 16384

    static int smset = 0;
    if (!smset) {
        cudaFuncSetAttribute(mma_main_kernel,
                             cudaFuncAttributeMaxDynamicSharedMemorySize, 2 * PBUF);
        cudaFuncSetAttribute(prep_mma_kernel,
                             cudaFuncAttributeMaxDynamicSharedMemorySize, 2 * PBUF);
        smset = 1;
    }

    wfrag_bias_kernel<<<144, 256>>>(Wcls, Wfl, benc, bcls, bfl);
    prep_mma_kernel<<<32 * NSPL, 128, 2 * PBUF>>>(Wenc);
    bsplit_kernel<<<32, 256>>>();
    mma_main_kernel<<<M / 64, 128, 2 * PBUF>>>(x, out);
}

// round 14
// speedup vs baseline: 1.0513x; 1.0043x over previous
#include <cuda_runtime.h>
#include <cuda_fp16.h>
#include <math.h>
#include <cstdint>

#define KTOT 2048
#define NJ   40
#define NT   5
#define NKC  128            // 2048/16 k-steps total
#define NBIAS 16
#define NSPL 8              // prep K-splits
#define SMARGIN 0.31f
#define RSCALE 2048.0f
#define RINV   (1.0f / 2048.0f)
#define PXB    17408u       // 64 rows * 272 B
#define BBYTES 10240u       // 640 uint2 hi + 640 uint2 lo per 64-k chunk
#define PBUF   (PXB + BBYTES)

// ---- device scratch -------------------------------------------------------
__device__ float g_c[NJ];
__device__ float g_cpart[NBIAS * NJ];
__device__ float g_part[NSPL * KTOT * NJ];
__device__ uint2 g_Wfh[NKC * NT * 32];   // Wp fragments fp16 hi
__device__ uint2 g_Wfl[NKC * NT * 32];   // Wp fragments fp16 residual*2048
__device__ uint2 g_Bfh[NKC * NT * 32];   // W12 fragments fp16 hi
__device__ uint2 g_Bfl[NKC * NT * 32];   // W12 fragments fp16 residual*2048

// ---- helpers --------------------------------------------------------------
__device__ __forceinline__ uint32_t smem_u32(const void* p) {
    uint32_t a;
    asm("{ .reg .u64 t; cvta.to.shared.u64 t, %1; cvt.u32.u64 %0, t; }" : "=r"(a) : "l"(p));
    return a;
}
__device__ __forceinline__ void cp_async16(uint32_t d, const void* s) {
    asm volatile("cp.async.cg.shared.global [%0], [%1], 16;" :: "r"(d), "l"(s));
}
__device__ __forceinline__ void cp_commit() { asm volatile("cp.async.commit_group;" ::: "memory"); }
__device__ __forceinline__ void cp_wait0()  { asm volatile("cp.async.wait_group 0;" ::: "memory"); }

#define MMA_F16(d, a0, a1, a2, a3, b0, b1)                                    \
    asm volatile("mma.sync.aligned.m16n8k16.row.col.f32.f16.f16.f32 "         \
                 "{%0,%1,%2,%3}, {%4,%5,%6,%7}, {%8,%9}, {%0,%1,%2,%3};\n"    \
                 : "+f"(d[0]), "+f"(d[1]), "+f"(d[2]), "+f"(d[3])             \
                 : "r"(a0), "r"(a1), "r"(a2), "r"(a3), "r"(b0), "r"(b1))

__device__ __forceinline__ void cvt_split_h(float2 v, unsigned& h, unsigned& l) {
    __half2 hh = __floats2half2_rn(v.x, v.y);
    float2 hf = __half22float2(hh);
    __half2 ll = __floats2half2_rn((v.x - hf.x) * RSCALE, (v.y - hf.y) * RSCALE);
    h = *reinterpret_cast<unsigned*>(&hh);
    l = *reinterpret_cast<unsigned*>(&ll);
}
__device__ __forceinline__ unsigned pack_h2(float a, float b) {
    __half2 h = __floats2half2_rn(a, b);
    return *reinterpret_cast<unsigned*>(&h);
}

// ---------------------------------------------------------------------------
// Kernel A: blocks 0..127 pack Wp=[Wcls|Wfl] into fp16 hi/lo MMA fragments;
//           blocks 128..143 bias partials; block 128 inits g_c raw biases.
// ---------------------------------------------------------------------------
__global__ __launch_bounds__(256)
void wfrag_bias_kernel(const float* __restrict__ Wcls, const float* __restrict__ Wfl,
                       const float* __restrict__ benc,
                       const float* __restrict__ bcls, const float* __restrict__ bfl) {
    int b = blockIdx.x;
    int tid = threadIdx.x;
    if (b < 128) {                       // one 16-row kc16 slab per block
        __shared__ float wp[16 * NJ];
        for (int i = tid; i < 16 * NJ; i += 256) {
            int m = i / NJ, n = i - (i / NJ) * NJ;
            int gm = b * 16 + m;
            wp[i] = (n < 20) ? Wcls[(size_t)gm * 20 + n] : Wfl[(size_t)gm * 20 + (n - 20)];
        }
        __syncthreads();
        if (tid < 160) {
            int lane = tid & 31, nt = tid >> 5;
            int m0 = (lane & 3) * 2, n = nt * 8 + (lane >> 2);
            float v[4], rr[4];
#pragma unroll
            for (int e = 0; e < 4; e++) {
                v[e] = wp[(m0 + (e >> 1) * 8 + (e & 1)) * NJ + n];
                __half h = __float2half_rn(v[e]);
                rr[e] = (v[e] - __half2float(h)) * RSCALE;
            }
            int gi = b * 160 + tid;
            g_Wfh[gi] = make_uint2(pack_h2(v[0], v[1]), pack_h2(v[2], v[3]));
            g_Wfl[gi] = make_uint2(pack_h2(rr[0], rr[1]), pack_h2(rr[2], rr[3]));
        }
        return;
    }
    // bias blocks
    __shared__ float sw[4][NJ];
    int bb = b - 128;
    if (tid >= 128) return;
    int k = bb * 128 + tid;
    int warp = tid >> 5, lane = tid & 31;
    float bv = benc[k];
    float w[NJ];
#pragma unroll
    for (int j4 = 0; j4 < 5; j4++) {
        float4 v = *(const float4*)(Wcls + (size_t)k * 20 + j4 * 4);
        w[j4*4+0] = v.x; w[j4*4+1] = v.y; w[j4*4+2] = v.z; w[j4*4+3] = v.w;
    }
#pragma unroll
    for (int j4 = 0; j4 < 5; j4++) {
        float4 v = *(const float4*)(Wfl + (size_t)k * 20 + j4 * 4);
        w[20+j4*4+0] = v.x; w[20+j4*4+1] = v.y; w[20+j4*4+2] = v.z; w[20+j4*4+3] = v.w;
    }
#pragma unroll
    for (int j = 0; j < NJ; j++) {
        float s = bv * w[j];
#pragma unroll
        for (int o = 16; o > 0; o >>= 1) s += __shfl_xor_sync(0xffffffffu, s, o);
        if (lane == 0) sw[warp][j] = s;
    }
    __syncthreads();
    if (tid < NJ) {
        g_cpart[bb * NJ + tid] = (sw[0][tid] + sw[1][tid]) + (sw[2][tid] + sw[3][tid]);
        if (bb == 0) g_c[tid] = (tid < 20) ? bcls[tid] : bfl[tid - 20];
    }
}

// ---------------------------------------------------------------------------
// 64-row staging helpers (128-thread and 256-thread variants)
// ---------------------------------------------------------------------------
__device__ __forceinline__ void stage64(uint32_t smb, int buf, int gchunk,
                                        const float* __restrict__ src, size_t rowbase,
                                        const uint2* __restrict__ fh,
                                        const uint2* __restrict__ fl, int tid) {
    uint32_t xd = smb + (uint32_t)buf * PBUF;
#pragma unroll
    for (int it = 0; it < 8; it++) {
        int q = it * 128 + tid;
        int rw = q >> 4, c4 = q & 15;
        cp_async16(xd + (uint32_t)(rw * 272 + c4 * 16),
                   src + (rowbase + rw) * KTOT + gchunk * 64 + c4 * 4);
    }
    uint32_t bd = xd + PXB;
    const char* srcH = (const char*)(fh + (size_t)gchunk * 640);
    const char* srcL = (const char*)(fl + (size_t)gchunk * 640);
#pragma unroll
    for (int it = 0; it < 5; it++) {
        int q = it * 128 + tid;
        if (q < 320) cp_async16(bd + (uint32_t)q * 16, srcH + q * 16);
        else         cp_async16(bd + 5120u + (uint32_t)(q - 320) * 16, srcL + (q - 320) * 16);
    }
}

__device__ __forceinline__ void stage64_256(uint32_t smb, int buf, int gchunk,
                                            const float* __restrict__ src, size_t rowbase,
                                            const uint2* __restrict__ fh,
                                            const uint2* __restrict__ fl, int tid) {
    uint32_t xd = smb + (uint32_t)buf * PBUF;
#pragma unroll
    for (int it = 0; it < 4; it++) {
        int q = it * 256 + tid;
        int rw = q >> 4, c4 = q & 15;
        cp_async16(xd + (uint32_t)(rw * 272 + c4 * 16),
                   src + (rowbase + rw) * KTOT + gchunk * 64 + c4 * 4);
    }
    uint32_t bd = xd + PXB;
    const char* srcH = (const char*)(fh + (size_t)gchunk * 640);
    const char* srcL = (const char*)(fl + (size_t)gchunk * 640);
#pragma unroll
    for (int it = 0; it < 3; it++) {
        int q = it * 256 + tid;
        if (q < 320)      cp_async16(bd + (uint32_t)q * 16, srcH + q * 16);
        else if (q < 640) cp_async16(bd + 5120u + (uint32_t)(q - 320) * 16, srcL + (q - 320) * 16);
    }
}

// ---------------------------------------------------------------------------
// Kernel B: prep GEMM  g_part[split] = W_enc @ Wp  using pre-packed fragments.
// grid 256 = 32 m-tiles (64 rows) x 8 K-splits, 128 threads, 4 chunks each.
// ---------------------------------------------------------------------------
__global__ __launch_bounds__(128)
void prep_mma_kernel(const float* __restrict__ Wenc) {
    extern __shared__ char sm[];
    const int tid = threadIdx.x;
    const int warp = tid >> 5, lane = tid & 31;
    const int c2 = (lane & 3) * 2;
    const int tile = blockIdx.x & 31, split = blockIdx.x >> 5;
    const size_t tilebase = (size_t)tile * 64;
    const int chunk0 = split * 4;

    const uint32_t smb = smem_u32(sm);
    stage64(smb, 0, chunk0, Wenc, tilebase, g_Wfh, g_Wfl, tid);
    cp_commit(); cp_wait0();
    __syncthreads();

    float acc1[NT][4], acc2[NT][4];
#pragma unroll
    for (int nt = 0; nt < NT; nt++)
#pragma unroll
        for (int e = 0; e < 4; e++) { acc1[nt][e] = 0.f; acc2[nt][e] = 0.f; }

    const uint32_t xoff = (uint32_t)((warp * 16 + (lane >> 2)) * 272 + c2 * 4);

    for (int c = 0; c < 4; c++) {
        int buf = c & 1;
        if (c + 1 < 4) { stage64(smb, buf ^ 1, chunk0 + c + 1, Wenc, tilebase, g_Wfh, g_Wfl, tid); cp_commit(); }
        uint32_t base = smb + (uint32_t)buf * PBUF;
        uint32_t xa = base + xoff;
        uint32_t ba = base + PXB + (uint32_t)lane * 8;
#pragma unroll
        for (int s = 0; s < 4; s++) {
            float2 v00, v10, v01, v11;
            asm("ld.shared.v2.f32 {%0, %1}, [%2];" : "=f"(v00.x), "=f"(v00.y) : "r"(xa + s * 64));
            asm("ld.shared.v2.f32 {%0, %1}, [%2];" : "=f"(v10.x), "=f"(v10.y) : "r"(xa + s * 64 + 8 * 272));
            asm("ld.shared.v2.f32 {%0, %1}, [%2];" : "=f"(v01.x), "=f"(v01.y) : "r"(xa + s * 64 + 32));
            asm("ld.shared.v2.f32 {%0, %1}, [%2];" : "=f"(v11.x), "=f"(v11.y) : "r"(xa + s * 64 + 32 + 8 * 272));
            unsigned ah0, ah1, ah2, ah3, al0, al1, al2, al3;
            cvt_split_h(v00, ah0, al0);
            cvt_split_h(v10, ah1, al1);
            cvt_split_h(v01, ah2, al2);
            cvt_split_h(v11, ah3, al3);
#pragma unroll
            for (int nt = 0; nt < NT; nt++) {
                uint2 wh, wl;
                uint32_t fo = (uint32_t)((s * NT + nt) * 32) * 8;
                asm("ld.shared.v2.u32 {%0, %1}, [%2];" : "=r"(wh.x), "=r"(wh.y) : "r"(ba + fo));
                asm("ld.shared.v2.u32 {%0, %1}, [%2];" : "=r"(wl.x), "=r"(wl.y) : "r"(ba + fo + 5120));
                MMA_F16(acc1[nt], ah0, ah1, ah2, ah3, wh.x, wh.y);
                MMA_F16(acc2[nt], al0, al1, al2, al3, wh.x, wh.y);
                MMA_F16(acc2[nt], ah0, ah1, ah2, ah3, wl.x, wl.y);
            }
        }
        if (c + 1 < 4) cp_wait0();
        __syncthreads();
    }

    int krow = (int)tilebase + warp * 16 + (lane >> 2);
#pragma unroll
    for (int nt = 0; nt < NT; nt++) {
        float* p0 = g_part + ((size_t)split * KTOT + krow) * NJ + nt * 8 + c2;
        float* p1 = p0 + 8 * NJ;
        *(float2*)p0 = make_float2(acc1[nt][0] + acc2[nt][0] * RINV,
                                   acc1[nt][1] + acc2[nt][1] * RINV);
        *(float2*)p1 = make_float2(acc1[nt][2] + acc2[nt][2] * RINV,
                                   acc1[nt][3] + acc2[nt][3] * RINV);
    }
}

// ---------------------------------------------------------------------------
// Kernel C: coalesced reduce of 8 partial slabs -> W12 fragment pack.
// ---------------------------------------------------------------------------
__global__ __launch_bounds__(256)
void bsplit_kernel() {
    int b = blockIdx.x;                       // 0..31, 64-row W12 slab each
    int tid = threadIdx.x;
    __shared__ float w12[64 * NJ];
    float r[10];
#pragma unroll
    for (int i = 0; i < 10; i++) r[i] = 0.f;
    size_t cellbase = (size_t)b * 2560;
#pragma unroll
    for (int s = 0; s < NSPL; s++) {
        const float* src = g_part + (size_t)s * (KTOT * NJ) + cellbase;
#pragma unroll
        for (int i = 0; i < 10; i++) r[i] += src[tid + i * 256];
    }
#pragma unroll
    for (int i = 0; i < 10; i++) w12[tid + i * 256] = r[i];
    __syncthreads();
#pragma unroll
    for (int i = 0; i < 3; i++) {
        int f = tid + i * 256;
        if (f < 640) {
            int kc16l = f / 160;
            int rem = f - kc16l * 160;
            int nt = rem >> 5, lane = rem & 31;
            int k0l = kc16l * 16 + (lane & 3) * 2;
            int n = nt * 8 + (lane >> 2);
            float v[4], rr[4];
#pragma unroll
            for (int e = 0; e < 4; e++) {
                v[e] = w12[(k0l + (e >> 1) * 8 + (e & 1)) * NJ + n];
                __half h = __float2half_rn(v[e]);
                rr[e] = (v[e] - __half2float(h)) * RSCALE;
            }
            int gi = b * 640 + f;
            g_Bfh[gi] = make_uint2(pack_h2(v[0], v[1]), pack_h2(v[2], v[3]));
            g_Bfl[gi] = make_uint2(pack_h2(rr[0], rr[1]), pack_h2(rr[2], rr[3]));
        }
    }
}

// ---------------------------------------------------------------------------
// Main kernel: 64 rows / 256 threads (8 warps) / grid 256.
// Warps 0-3: rows, k-steps s=0,1 of each chunk.  Warps 4-7: same rows,
// s=2,3.  Doubles resident warps (1024 -> 2048) to hide LDS/cvt/MMA latency.
// K-halves combined in fp32 via smem, then the validated fused epilogue.
// ---------------------------------------------------------------------------
__global__ __launch_bounds__(256)
void mma_main_kernel(const float* __restrict__ x, float* __restrict__ out) {
    extern __shared__ char sm[];
    __shared__ float cb[NJ];
    const int tid = threadIdx.x;
    const int warp = tid >> 5, lane = tid & 31;
    const int rw = warp & 3, kh = warp >> 2;
    const int c2 = (lane & 3) * 2;
    const size_t growbase = (size_t)blockIdx.x * 64;

    if (tid < NJ) {
        float s = g_c[tid];
#pragma unroll
        for (int p = 0; p < NBIAS; p++) s += g_cpart[p * NJ + tid];
        cb[tid] = s;
    }

    const uint32_t smb = smem_u32(sm);
    stage64_256(smb, 0, 0, x, growbase, g_Bfh, g_Bfl, tid);
    cp_commit(); cp_wait0();
    __syncthreads();

    float acc1[NT][4], acc2[NT][4];
#pragma unroll
    for (int nt = 0; nt < NT; nt++)
#pragma unroll
        for (int e = 0; e < 4; e++) { acc1[nt][e] = 0.f; acc2[nt][e] = 0.f; }

    const uint32_t xoff = (uint32_t)((rw * 16 + (lane >> 2)) * 272 + c2 * 4);

    for (int c = 0; c < 32; c++) {
        int buf = c & 1;
        if (c + 1 < 32) { stage64_256(smb, buf ^ 1, c + 1, x, growbase, g_Bfh, g_Bfl, tid); cp_commit(); }
        uint32_t base = smb + (uint32_t)buf * PBUF;
        uint32_t xa = base + xoff;
        uint32_t ba = base + PXB + (uint32_t)lane * 8;
#pragma unroll
        for (int ss = 0; ss < 2; ss++) {
            int s = kh * 2 + ss;
            float2 v00, v10, v01, v11;
            asm("ld.shared.v2.f32 {%0, %1}, [%2];" : "=f"(v00.x), "=f"(v00.y) : "r"(xa + s * 64));
            asm("ld.shared.v2.f32 {%0, %1}, [%2];" : "=f"(v10.x), "=f"(v10.y) : "r"(xa + s * 64 + 8 * 272));
            asm("ld.shared.v2.f32 {%0, %1}, [%2];" : "=f"(v01.x), "=f"(v01.y) : "r"(xa + s * 64 + 32));
            asm("ld.shared.v2.f32 {%0, %1}, [%2];" : "=f"(v11.x), "=f"(v11.y) : "r"(xa + s * 64 + 32 + 8 * 272));
            unsigned ah0, ah1, ah2, ah3, al0, al1, al2, al3;
            cvt_split_h(v00, ah0, al0);
            cvt_split_h(v10, ah1, al1);
            cvt_split_h(v01, ah2, al2);
            cvt_split_h(v11, ah3, al3);
#pragma unroll
            for (int nt = 0; nt < NT; nt++) {
                uint2 wh, wl;
                uint32_t fo = (uint32_t)((s * NT + nt) * 32) * 8;
                asm("ld.shared.v2.u32 {%0, %1}, [%2];" : "=r"(wh.x), "=r"(wh.y) : "r"(ba + fo));
                asm("ld.shared.v2.u32 {%0, %1}, [%2];" : "=r"(wl.x), "=r"(wl.y) : "r"(ba + fo + 5120));
                MMA_F16(acc1[nt], ah0, ah1, ah2, ah3, wh.x, wh.y);
                MMA_F16(acc2[nt], al0, al1, al2, al3, wh.x, wh.y);
                MMA_F16(acc2[nt], ah0, ah1, ah2, ah3, wl.x, wl.y);
            }
        }
        if (c + 1 < 32) cp_wait0();
        __syncthreads();
    }

    // ---- combine k-halves via smem (stride 21 floats: conflict-free) ------
    float* ex = (float*)sm;                 // reuse buffer memory (post-sync)
    if (kh == 1) {
        float* dst = ex + (size_t)(rw * 32 + lane) * 21;
#pragma unroll
        for (int nt = 0; nt < NT; nt++)
#pragma unroll
            for (int e = 0; e < 4; e++)
                dst[nt * 4 + e] = acc1[nt][e] + acc2[nt][e] * RINV;
    }
    __syncthreads();
    if (kh == 1) return;

    float fin[NT][4];
    {
        const float* src = ex + (size_t)(rw * 32 + lane) * 21;
#pragma unroll
        for (int nt = 0; nt < NT; nt++)
#pragma unroll
            for (int e = 0; e < 4; e++)
                fin[nt][e] = acc1[nt][e] + acc2[nt][e] * RINV + src[nt * 4 + e];
    }

    // ---- epilogue (validated): dual softmax + threshold -------------------
    int row0 = (int)growbase + rw * 16 + (lane >> 2);
    float scl[2];
    float ecls[2][6];
#pragma unroll
    for (int half = 0; half < 2; half++) {
        float m1 = -1e30f, m2 = -1e30f, mn2 = 1e30f;
#pragma unroll
        for (int nt = 0; nt < NT; nt++)
#pragma unroll
            for (int e = 0; e < 2; e++) {
                int j = nt * 8 + c2 + e;
                float v = fin[nt][half * 2 + e] + cb[j];
                if (j < 20) m1 = fmaxf(m1, v);
                else { m2 = fmaxf(m2, v); mn2 = fminf(mn2, v); }
            }
        m1 = fmaxf(m1, __shfl_xor_sync(0xffffffffu, m1, 1));
        m1 = fmaxf(m1, __shfl_xor_sync(0xffffffffu, m1, 2));
        m2 = fmaxf(m2, __shfl_xor_sync(0xffffffffu, m2, 1));
        m2 = fmaxf(m2, __shfl_xor_sync(0xffffffffu, m2, 2));
        mn2 = fminf(mn2, __shfl_xor_sync(0xffffffffu, mn2, 1));
        mn2 = fminf(mn2, __shfl_xor_sync(0xffffffffu, mn2, 2));
        float s1 = 0.f, s2 = 0.f;
#pragma unroll
        for (int nt = 0; nt < NT; nt++)
#pragma unroll
            for (int e = 0; e < 2; e++) {
                int j = nt * 8 + c2 + e;
                float v = fin[nt][half * 2 + e] + cb[j];
                if (j < 20) {
                    float ex2 = __expf(v - m1);
                    if (nt < 3) ecls[half][nt * 2 + e] = ex2;
                    s1 += ex2;
                } else {
                    s2 += __expf(v - m2);
                }
            }
        s1 += __shfl_xor_sync(0xffffffffu, s1, 1);
        s1 += __shfl_xor_sync(0xffffffffu, s1, 2);
        s2 += __shfl_xor_sync(0xffffffffu, s2, 1);
        s2 += __shfl_xor_sync(0xffffffffu, s2, 2);
        float pred = 1.0f / s1;
        float tau  = __expf(mn2 - m2) / s2;
        scl[half] = (pred >= tau + SMARGIN) ? pred : 0.0f;
    }
#pragma unroll
    for (int half = 0; half < 2; half++) {
        float* orow = out + (size_t)(row0 + half * 8) * 20;
#pragma unroll
        for (int nt = 0; nt < 3; nt++) {
            int j0 = nt * 8 + c2;
            if (j0 < 20)
                *(float2*)(orow + j0) = make_float2(ecls[half][nt * 2 + 0] * scl[half],
                                                    ecls[half][nt * 2 + 1] * scl[half]);
        }
    }
}

// ---------------------------------------------------------------------------
extern "C" void kernel_launch(void* const* d_in, const int* in_sizes, int n_in,
                              void* d_out, int out_size) {
    const float* x    = (const float*)d_in[0];
    const float* Wenc = (const float*)d_in[1];
    const float* benc = (const float*)d_in[2];
    const float* Wcls = (const float*)d_in[3];
    const float* bcls = (const float*)d_in[4];
    const float* Wfl  = (const float*)d_in[5];
    const float* bfl  = (const float*)d_in[6];
    float* out = (float*)d_out;
    int M = in_sizes[0] / KTOT;   // 16384

    static int smset = 0;
    if (!smset) {
        cudaFuncSetAttribute(mma_main_kernel,
                             cudaFuncAttributeMaxDynamicSharedMemorySize, 2 * PBUF);
        cudaFuncSetAttribute(prep_mma_kernel,
                             cudaFuncAttributeMaxDynamicSharedMemorySize, 2 * PBUF);
        smset = 1;
    }

    wfrag_bias_kernel<<<144, 256>>>(Wcls, Wfl, benc, bcls, bfl);
    prep_mma_kernel<<<32 * NSPL, 128, 2 * PBUF>>>(Wenc);
    bsplit_kernel<<<32, 256>>>();
    mma_main_kernel<<<M / 64, 256, 2 * PBUF>>>(x, out);
}

// round 15
// speedup vs baseline: 1.0849x; 1.0320x over previous
#include <cuda_runtime.h>
#include <cuda_fp16.h>
#include <math.h>
#include <cstdint>

#define KTOT 2048
#define NJ   40
#define NT   5
#define NKC  128            // 2048/16 k-steps total
#define NBIAS 16
#define NSPL 8              // prep K-splits
#define SMARGIN 0.31f
#define RSCALE 2048.0f
#define RINV   (1.0f / 2048.0f)
#define PXB    17408u       // 64 rows * 272 B
#define BBYTES 10240u       // 640 uint4 interleaved hi/lo fragments
#define PBUF   (PXB + BBYTES)

// ---- device scratch -------------------------------------------------------
__device__ float g_c[NJ];
__device__ float g_cpart[NBIAS * NJ];
__device__ float g_part[NSPL * KTOT * NJ];
__device__ uint4 g_Wf[NKC * NT * 32];   // Wp frags  {hi.x,hi.y,lo.x,lo.y}
__device__ uint4 g_Bf[NKC * NT * 32];   // W12 frags {hi.x,hi.y,lo.x,lo.y}

// ---- helpers --------------------------------------------------------------
__device__ __forceinline__ uint32_t smem_u32(const void* p) {
    uint32_t a;
    asm("{ .reg .u64 t; cvta.to.shared.u64 t, %1; cvt.u32.u64 %0, t; }" : "=r"(a) : "l"(p));
    return a;
}
__device__ __forceinline__ void cp_async16(uint32_t d, const void* s) {
    asm volatile("cp.async.cg.shared.global [%0], [%1], 16;" :: "r"(d), "l"(s));
}
__device__ __forceinline__ void cp_commit() { asm volatile("cp.async.commit_group;" ::: "memory"); }
__device__ __forceinline__ void cp_wait0()  { asm volatile("cp.async.wait_group 0;" ::: "memory"); }
__device__ __forceinline__ void cp_wait1()  { asm volatile("cp.async.wait_group 1;" ::: "memory"); }

#define MMA_F16(d, a0, a1, a2, a3, b0, b1)                                    \
    asm volatile("mma.sync.aligned.m16n8k16.row.col.f32.f16.f16.f32 "         \
                 "{%0,%1,%2,%3}, {%4,%5,%6,%7}, {%8,%9}, {%0,%1,%2,%3};\n"    \
                 : "+f"(d[0]), "+f"(d[1]), "+f"(d[2]), "+f"(d[3])             \
                 : "r"(a0), "r"(a1), "r"(a2), "r"(a3), "r"(b0), "r"(b1))

__device__ __forceinline__ void cvt_split_h(float2 v, unsigned& h, unsigned& l) {
    __half2 hh = __floats2half2_rn(v.x, v.y);
    float2 hf = __half22float2(hh);
    __half2 ll = __floats2half2_rn((v.x - hf.x) * RSCALE, (v.y - hf.y) * RSCALE);
    h = *reinterpret_cast<unsigned*>(&hh);
    l = *reinterpret_cast<unsigned*>(&ll);
}
__device__ __forceinline__ unsigned pack_h2(float a, float b) {
    __half2 h = __floats2half2_rn(a, b);
    return *reinterpret_cast<unsigned*>(&h);
}
__device__ __forceinline__ uint4 make_frag(const float v[4]) {
    float rr[4];
#pragma unroll
    for (int e = 0; e < 4; e++) {
        __half h = __float2half_rn(v[e]);
        rr[e] = (v[e] - __half2float(h)) * RSCALE;
    }
    return make_uint4(pack_h2(v[0], v[1]), pack_h2(v[2], v[3]),
                      pack_h2(rr[0], rr[1]), pack_h2(rr[2], rr[3]));
}

// ---------------------------------------------------------------------------
// Kernel A: blocks 0..127 pack Wp=[Wcls|Wfl] into interleaved fragments;
//           blocks 128..143 bias partials; block 128 inits g_c raw biases.
// ---------------------------------------------------------------------------
__global__ __launch_bounds__(256)
void wfrag_bias_kernel(const float* __restrict__ Wcls, const float* __restrict__ Wfl,
                       const float* __restrict__ benc,
                       const float* __restrict__ bcls, const float* __restrict__ bfl) {
    int b = blockIdx.x;
    int tid = threadIdx.x;
    if (b < 128) {                       // one 16-row kc16 slab per block
        __shared__ float wp[16 * NJ];
        for (int i = tid; i < 16 * NJ; i += 256) {
            int m = i / NJ, n = i - (i / NJ) * NJ;
            int gm = b * 16 + m;
            wp[i] = (n < 20) ? Wcls[(size_t)gm * 20 + n] : Wfl[(size_t)gm * 20 + (n - 20)];
        }
        __syncthreads();
        if (tid < 160) {
            int lane = tid & 31, nt = tid >> 5;
            int m0 = (lane & 3) * 2, n = nt * 8 + (lane >> 2);
            float v[4];
#pragma unroll
            for (int e = 0; e < 4; e++)
                v[e] = wp[(m0 + (e >> 1) * 8 + (e & 1)) * NJ + n];
            g_Wf[b * 160 + tid] = make_frag(v);
        }
        return;
    }
    // bias blocks
    __shared__ float sw[4][NJ];
    int bb = b - 128;
    if (tid >= 128) return;
    int k = bb * 128 + tid;
    int warp = tid >> 5, lane = tid & 31;
    float bv = benc[k];
    float w[NJ];
#pragma unroll
    for (int j4 = 0; j4 < 5; j4++) {
        float4 v = *(const float4*)(Wcls + (size_t)k * 20 + j4 * 4);
        w[j4*4+0] = v.x; w[j4*4+1] = v.y; w[j4*4+2] = v.z; w[j4*4+3] = v.w;
    }
#pragma unroll
    for (int j4 = 0; j4 < 5; j4++) {
        float4 v = *(const float4*)(Wfl + (size_t)k * 20 + j4 * 4);
        w[20+j4*4+0] = v.x; w[20+j4*4+1] = v.y; w[20+j4*4+2] = v.z; w[20+j4*4+3] = v.w;
    }
#pragma unroll
    for (int j = 0; j < NJ; j++) {
        float s = bv * w[j];
#pragma unroll
        for (int o = 16; o > 0; o >>= 1) s += __shfl_xor_sync(0xffffffffu, s, o);
        if (lane == 0) sw[warp][j] = s;
    }
    __syncthreads();
    if (tid < NJ) {
        g_cpart[bb * NJ + tid] = (sw[0][tid] + sw[1][tid]) + (sw[2][tid] + sw[3][tid]);
        if (bb == 0) g_c[tid] = (tid < 20) ? bcls[tid] : bfl[tid - 20];
    }
}

// ---------------------------------------------------------------------------
// 64-row staging helpers
// ---------------------------------------------------------------------------
__device__ __forceinline__ void stage64(uint32_t smb, int buf, int gchunk,
                                        const float* __restrict__ src, size_t rowbase,
                                        const uint4* __restrict__ frag, int tid) {
    uint32_t xd = smb + (uint32_t)buf * PBUF;
#pragma unroll
    for (int it = 0; it < 8; it++) {
        int q = it * 128 + tid;
        int rw = q >> 4, c4 = q & 15;
        cp_async16(xd + (uint32_t)(rw * 272 + c4 * 16),
                   src + (rowbase + rw) * KTOT + gchunk * 64 + c4 * 4);
    }
    uint32_t bd = xd + PXB;
    const uint4* fsrc = frag + (size_t)gchunk * 640;
#pragma unroll
    for (int it = 0; it < 5; it++) {
        int q = it * 128 + tid;
        cp_async16(bd + (uint32_t)q * 16, fsrc + q);
    }
}

__device__ __forceinline__ void stage64_256(uint32_t smb, int buf, int gchunk,
                                            const float* __restrict__ src, size_t rowbase,
                                            const uint4* __restrict__ frag, int tid) {
    uint32_t xd = smb + (uint32_t)buf * PBUF;
#pragma unroll
    for (int it = 0; it < 4; it++) {
        int q = it * 256 + tid;
        int rw = q >> 4, c4 = q & 15;
        cp_async16(xd + (uint32_t)(rw * 272 + c4 * 16),
                   src + (rowbase + rw) * KTOT + gchunk * 64 + c4 * 4);
    }
    uint32_t bd = xd + PXB;
    const uint4* fsrc = frag + (size_t)gchunk * 640;
#pragma unroll
    for (int it = 0; it < 3; it++) {
        int q = it * 256 + tid;
        if (q < 640) cp_async16(bd + (uint32_t)q * 16, fsrc + q);
    }
}

// ---------------------------------------------------------------------------
// Kernel B: prep GEMM  g_part[split] = W_enc @ Wp  using interleaved frags.
// grid 256 = 32 m-tiles (64 rows) x 8 K-splits, 128 threads, 4 chunks each.
// ---------------------------------------------------------------------------
__global__ __launch_bounds__(128)
void prep_mma_kernel(const float* __restrict__ Wenc) {
    extern __shared__ char sm[];
    const int tid = threadIdx.x;
    const int warp = tid >> 5, lane = tid & 31;
    const int c2 = (lane & 3) * 2;
    const int tile = blockIdx.x & 31, split = blockIdx.x >> 5;
    const size_t tilebase = (size_t)tile * 64;
    const int chunk0 = split * 4;

    const uint32_t smb = smem_u32(sm);
    stage64(smb, 0, chunk0, Wenc, tilebase, g_Wf, tid);
    cp_commit(); cp_wait0();
    __syncthreads();

    float acc1[NT][4], acc2[NT][4];
#pragma unroll
    for (int nt = 0; nt < NT; nt++)
#pragma unroll
        for (int e = 0; e < 4; e++) { acc1[nt][e] = 0.f; acc2[nt][e] = 0.f; }

    const uint32_t xoff = (uint32_t)((warp * 16 + (lane >> 2)) * 272 + c2 * 4);

    for (int c = 0; c < 4; c++) {
        int buf = c & 1;
        if (c + 1 < 4) { stage64(smb, buf ^ 1, chunk0 + c + 1, Wenc, tilebase, g_Wf, tid); cp_commit(); }
        uint32_t base = smb + (uint32_t)buf * PBUF;
        uint32_t xa = base + xoff;
        uint32_t ba = base + PXB + (uint32_t)lane * 16;
#pragma unroll
        for (int s = 0; s < 4; s++) {
            float2 v00, v10, v01, v11;
            asm("ld.shared.v2.f32 {%0, %1}, [%2];" : "=f"(v00.x), "=f"(v00.y) : "r"(xa + s * 64));
            asm("ld.shared.v2.f32 {%0, %1}, [%2];" : "=f"(v10.x), "=f"(v10.y) : "r"(xa + s * 64 + 8 * 272));
            asm("ld.shared.v2.f32 {%0, %1}, [%2];" : "=f"(v01.x), "=f"(v01.y) : "r"(xa + s * 64 + 32));
            asm("ld.shared.v2.f32 {%0, %1}, [%2];" : "=f"(v11.x), "=f"(v11.y) : "r"(xa + s * 64 + 32 + 8 * 272));
            unsigned ah0, ah1, ah2, ah3, al0, al1, al2, al3;
            cvt_split_h(v00, ah0, al0);
            cvt_split_h(v10, ah1, al1);
            cvt_split_h(v01, ah2, al2);
            cvt_split_h(v11, ah3, al3);
#pragma unroll
            for (int nt = 0; nt < NT; nt++) {
                uint4 w;
                uint32_t fo = (uint32_t)((s * NT + nt) * 512);
                asm("ld.shared.v4.u32 {%0, %1, %2, %3}, [%4];"
                    : "=r"(w.x), "=r"(w.y), "=r"(w.z), "=r"(w.w) : "r"(ba + fo));
                MMA_F16(acc1[nt], ah0, ah1, ah2, ah3, w.x, w.y);
                MMA_F16(acc2[nt], al0, al1, al2, al3, w.x, w.y);
                MMA_F16(acc2[nt], ah0, ah1, ah2, ah3, w.z, w.w);
            }
        }
        if (c + 1 < 4) cp_wait0();
        __syncthreads();
    }

    int krow = (int)tilebase + warp * 16 + (lane >> 2);
#pragma unroll
    for (int nt = 0; nt < NT; nt++) {
        float* p0 = g_part + ((size_t)split * KTOT + krow) * NJ + nt * 8 + c2;
        float* p1 = p0 + 8 * NJ;
        *(float2*)p0 = make_float2(acc1[nt][0] + acc2[nt][0] * RINV,
                                   acc1[nt][1] + acc2[nt][1] * RINV);
        *(float2*)p1 = make_float2(acc1[nt][2] + acc2[nt][2] * RINV,
                                   acc1[nt][3] + acc2[nt][3] * RINV);
    }
}

// ---------------------------------------------------------------------------
// Kernel C: coalesced reduce of 8 partial slabs -> interleaved W12 fragments.
// ---------------------------------------------------------------------------
__global__ __launch_bounds__(256)
void bsplit_kernel() {
    int b = blockIdx.x;                       // 0..31, 64-row W12 slab each
    int tid = threadIdx.x;
    __shared__ float w12[64 * NJ];
    float r[10];
#pragma unroll
    for (int i = 0; i < 10; i++) r[i] = 0.f;
    size_t cellbase = (size_t)b * 2560;
#pragma unroll
    for (int s = 0; s < NSPL; s++) {
        const float* src = g_part + (size_t)s * (KTOT * NJ) + cellbase;
#pragma unroll
        for (int i = 0; i < 10; i++) r[i] += src[tid + i * 256];
    }
#pragma unroll
    for (int i = 0; i < 10; i++) w12[tid + i * 256] = r[i];
    __syncthreads();
#pragma unroll
    for (int i = 0; i < 3; i++) {
        int f = tid + i * 256;
        if (f < 640) {
            int kc16l = f / 160;
            int rem = f - kc16l * 160;
            int nt = rem >> 5, lane = rem & 31;
            int k0l = kc16l * 16 + (lane & 3) * 2;
            int n = nt * 8 + (lane >> 2);
            float v[4];
#pragma unroll
            for (int e = 0; e < 4; e++)
                v[e] = w12[(k0l + (e >> 1) * 8 + (e & 1)) * NJ + n];
            g_Bf[b * 640 + f] = make_frag(v);
        }
    }
}

// ---------------------------------------------------------------------------
// Main kernel: 64 rows / 256 threads / grid 256; warps 0-3 rows x k-steps 0-1,
// warps 4-7 same rows x k-steps 2-3.  3-stage cp.async pipeline (2-deep
// prefetch), interleaved-fragment LDS.128.  Validated fused epilogue.
// ---------------------------------------------------------------------------
__global__ __launch_bounds__(256)
void mma_main_kernel(const float* __restrict__ x, float* __restrict__ out) {
    extern __shared__ char sm[];
    __shared__ float cb[NJ];
    const int tid = threadIdx.x;
    const int warp = tid >> 5, lane = tid & 31;
    const int rw = warp & 3, kh = warp >> 2;
    const int c2 = (lane & 3) * 2;
    const size_t growbase = (size_t)blockIdx.x * 64;

    if (tid < NJ) {
        float s = g_c[tid];
#pragma unroll
        for (int p = 0; p < NBIAS; p++) s += g_cpart[p * NJ + tid];
        cb[tid] = s;
    }

    const uint32_t smb = smem_u32(sm);
    stage64_256(smb, 0, 0, x, growbase, g_Bf, tid); cp_commit();
    stage64_256(smb, 1, 1, x, growbase, g_Bf, tid); cp_commit();
    cp_wait1();
    __syncthreads();

    float acc1[NT][4], acc2[NT][4];
#pragma unroll
    for (int nt = 0; nt < NT; nt++)
#pragma unroll
        for (int e = 0; e < 4; e++) { acc1[nt][e] = 0.f; acc2[nt][e] = 0.f; }

    const uint32_t xoff = (uint32_t)((rw * 16 + (lane >> 2)) * 272 + c2 * 4);

    int buf = 0;
    for (int c = 0; c < 32; c++) {
        if (c + 2 < 32) {
            int nb = buf + 2; if (nb >= 3) nb -= 3;
            stage64_256(smb, nb, c + 2, x, growbase, g_Bf, tid);
            cp_commit();
        }
        uint32_t base = smb + (uint32_t)buf * PBUF;
        uint32_t xa = base + xoff;
        uint32_t ba = base + PXB + (uint32_t)lane * 16;
#pragma unroll
        for (int ss = 0; ss < 2; ss++) {
            int s = kh * 2 + ss;
            float2 v00, v10, v01, v11;
            asm("ld.shared.v2.f32 {%0, %1}, [%2];" : "=f"(v00.x), "=f"(v00.y) : "r"(xa + s * 64));
            asm("ld.shared.v2.f32 {%0, %1}, [%2];" : "=f"(v10.x), "=f"(v10.y) : "r"(xa + s * 64 + 8 * 272));
            asm("ld.shared.v2.f32 {%0, %1}, [%2];" : "=f"(v01.x), "=f"(v01.y) : "r"(xa + s * 64 + 32));
            asm("ld.shared.v2.f32 {%0, %1}, [%2];" : "=f"(v11.x), "=f"(v11.y) : "r"(xa + s * 64 + 32 + 8 * 272));
            unsigned ah0, ah1, ah2, ah3, al0, al1, al2, al3;
            cvt_split_h(v00, ah0, al0);
            cvt_split_h(v10, ah1, al1);
            cvt_split_h(v01, ah2, al2);
            cvt_split_h(v11, ah3, al3);
#pragma unroll
            for (int nt = 0; nt < NT; nt++) {
                uint4 w;
                uint32_t fo = (uint32_t)((s * NT + nt) * 512);
                asm("ld.shared.v4.u32 {%0, %1, %2, %3}, [%4];"
                    : "=r"(w.x), "=r"(w.y), "=r"(w.z), "=r"(w.w) : "r"(ba + fo));
                MMA_F16(acc1[nt], ah0, ah1, ah2, ah3, w.x, w.y);
                MMA_F16(acc2[nt], al0, al1, al2, al3, w.x, w.y);
                MMA_F16(acc2[nt], ah0, ah1, ah2, ah3, w.z, w.w);
            }
        }
        if (c + 1 < 32) {
            if (c + 2 < 32) cp_wait1(); else cp_wait0();
            __syncthreads();
        }
        if (++buf == 3) buf = 0;
    }

    // ---- combine k-halves via smem (stride 21 floats: conflict-free) ------
    float* ex = (float*)sm;                 // buffer 0 region; chunk31 used buf2
    if (kh == 1) {
        float* dst = ex + (size_t)(rw * 32 + lane) * 21;
#pragma unroll
        for (int nt = 0; nt < NT; nt++)
#pragma unroll
            for (int e = 0; e < 4; e++)
                dst[nt * 4 + e] = acc1[nt][e] + acc2[nt][e] * RINV;
    }
    __syncthreads();
    if (kh == 1) return;

    float fin[NT][4];
    {
        const float* src = ex + (size_t)(rw * 32 + lane) * 21;
#pragma unroll
        for (int nt = 0; nt < NT; nt++)
#pragma unroll
            for (int e = 0; e < 4; e++)
                fin[nt][e] = acc1[nt][e] + acc2[nt][e] * RINV + src[nt * 4 + e];
    }

    // ---- epilogue (validated): dual softmax + threshold -------------------
    int row0 = (int)growbase + rw * 16 + (lane >> 2);
    float scl[2];
    float ecls[2][6];
#pragma unroll
    for (int half = 0; half < 2; half++) {
        float m1 = -1e30f, m2 = -1e30f, mn2 = 1e30f;
#pragma unroll
        for (int nt = 0; nt < NT; nt++)
#pragma unroll
            for (int e = 0; e < 2; e++) {
                int j = nt * 8 + c2 + e;
                float v = fin[nt][half * 2 + e] + cb[j];
                if (j < 20) m1 = fmaxf(m1, v);
                else { m2 = fmaxf(m2, v); mn2 = fminf(mn2, v); }
            }
        m1 = fmaxf(m1, __shfl_xor_sync(0xffffffffu, m1, 1));
        m1 = fmaxf(m1, __shfl_xor_sync(0xffffffffu, m1, 2));
        m2 = fmaxf(m2, __shfl_xor_sync(0xffffffffu, m2, 1));
        m2 = fmaxf(m2, __shfl_xor_sync(0xffffffffu, m2, 2));
        mn2 = fminf(mn2, __shfl_xor_sync(0xffffffffu, mn2, 1));
        mn2 = fminf(mn2, __shfl_xor_sync(0xffffffffu, mn2, 2));
        float s1 = 0.f, s2 = 0.f;
#pragma unroll
        for (int nt = 0; nt < NT; nt++)
#pragma unroll
            for (int e = 0; e < 2; e++) {
                int j = nt * 8 + c2 + e;
                float v = fin[nt][half * 2 + e] + cb[j];
                if (j < 20) {
                    float ex2 = __expf(v - m1);
                    if (nt < 3) ecls[half][nt * 2 + e] = ex2;
                    s1 += ex2;
                } else {
                    s2 += __expf(v - m2);
                }
            }
        s1 += __shfl_xor_sync(0xffffffffu, s1, 1);
        s1 += __shfl_xor_sync(0xffffffffu, s1, 2);
        s2 += __shfl_xor_sync(0xffffffffu, s2, 1);
        s2 += __shfl_xor_sync(0xffffffffu, s2, 2);
        float pred = 1.0f / s1;
        float tau  = __expf(mn2 - m2) / s2;
        scl[half] = (pred >= tau + SMARGIN) ? pred : 0.0f;
    }
#pragma unroll
    for (int half = 0; half < 2; half++) {
        float* orow = out + (size_t)(row0 + half * 8) * 20;
#pragma unroll
        for (int nt = 0; nt < 3; nt++) {
            int j0 = nt * 8 + c2;
            if (j0 < 20)
                *(float2*)(orow + j0) = make_float2(ecls[half][nt * 2 + 0] * scl[half],
                                                    ecls[half][nt * 2 + 1] * scl[half]);
        }
    }
}

// ---------------------------------------------------------------------------
extern "C" void kernel_launch(void* const* d_in, const int* in_sizes, int n_in,
                              void* d_out, int out_size) {
    const float* x    = (const float*)d_in[0];
    const float* Wenc = (const float*)d_in[1];
    const float* benc = (const float*)d_in[2];
    const float* Wcls = (const float*)d_in[3];
    const float* bcls = (const float*)d_in[4];
    const float* Wfl  = (const float*)d_in[5];
    const float* bfl  = (const float*)d_in[6];
    float* out = (float*)d_out;
    int M = in_sizes[0] / KTOT;   // 16384

    static int smset = 0;
    if (!smset) {
        cudaFuncSetAttribute(mma_main_kernel,
                             cudaFuncAttributeMaxDynamicSharedMemorySize, 3 * PBUF);
        cudaFuncSetAttribute(prep_mma_kernel,
                             cudaFuncAttributeMaxDynamicSharedMemorySize, 2 * PBUF);
        smset = 1;
    }

    wfrag_bias_kernel<<<144, 256>>>(Wcls, Wfl, benc, bcls, bfl);
    prep_mma_kernel<<<32 * NSPL, 128, 2 * PBUF>>>(Wenc);
    bsplit_kernel<<<32, 256>>>();
    mma_main_kernel<<<M / 64, 256, 3 * PBUF>>>(x, out);
}